// round 1
// baseline (speedup 1.0000x reference)
#include <cuda_runtime.h>
#include <math.h>

#define BB 32
#define NN 16384
#define SS 8
#define DD 64
#define HH 128
#define TILES 32
#define ROWS_PB 512   // rows per block = 4 chunks of 128
#define CHUNK 128
#define LNEPS 1e-5f
#define EPSW  1e-8f

// ---------------- device scratch (no allocations allowed) ----------------
__device__ float  g_slots[BB * SS * DD];           // current slots
__device__ float4 g_qkgT4[BB * DD * SS / 4];       // qkg transposed [b][e][s], s contiguous
__device__ float  g_c1[BB * SS];
__device__ float  g_c2[BB * SS];
__device__ float4 g_Pp4[BB * TILES * SS * DD / 4]; // per-tile partial P [b][tile][s][d]
__device__ float  g_Ap[BB * TILES * SS];           // partial sum softmax
__device__ float  g_Qp[BB * TILES * SS];           // partial sum softmax*rstd*mean

__device__ __forceinline__ float sigmoidf_(float x) { return 1.0f / (1.0f + expf(-x)); }

// ---------------- init: slots = mu + exp(log_sigma) * noise ----------------
__global__ void k_init(const float* __restrict__ noise, const float* __restrict__ mu,
                       const float* __restrict__ lsig) {
    int b = blockIdx.x, t = threadIdx.x;
    for (int idx = t; idx < SS * DD; idx += blockDim.x)
        g_slots[b * 512 + idx] = mu[idx] + expf(lsig[idx]) * noise[b * 512 + idx];
}

// ---------------- per-iteration: q = LN(slots)@Wq^T * scale; qk = q@Wk; fold ln_in ----------------
__global__ void k_qk(const float* __restrict__ Wq, const float* __restrict__ Wk,
                     const float* __restrict__ g_slot, const float* __restrict__ b_slot,
                     const float* __restrict__ g_in, const float* __restrict__ b_in) {
    int b = blockIdx.x, t = threadIdx.x;
    int s = t >> 5, lane = t & 31;
    __shared__ float lns[SS][DD];
    __shared__ float qm[SS][DD];

    int e0 = lane, e1 = lane + 32;
    float v0 = g_slots[b * 512 + s * 64 + e0];
    float v1 = g_slots[b * 512 + s * 64 + e1];
    float sm = v0 + v1, sq = v0 * v0 + v1 * v1;
#pragma unroll
    for (int off = 16; off; off >>= 1) {
        sm += __shfl_xor_sync(0xffffffffu, sm, off);
        sq += __shfl_xor_sync(0xffffffffu, sq, off);
    }
    float mean = sm * (1.0f / 64.0f);
    float var  = sq * (1.0f / 64.0f) - mean * mean;
    float rstd = rsqrtf(var + LNEPS);
    lns[s][e0] = (v0 - mean) * rstd * g_slot[e0] + b_slot[e0];
    lns[s][e1] = (v1 - mean) * rstd * g_slot[e1] + b_slot[e1];
    __syncthreads();

    // q[s,d] = scale * sum_e lns[s,e] * Wq[d,e]   (d = lane, lane+32)
    float q0 = 0.f, q1 = 0.f;
#pragma unroll 8
    for (int e = 0; e < 64; e++) {
        float l = lns[s][e];
        q0 += l * Wq[e0 * 64 + e];
        q1 += l * Wq[e1 * 64 + e];
    }
    qm[s][e0] = q0 * 0.125f;   // D^-0.5 = 1/8
    qm[s][e1] = q1 * 0.125f;
    __syncthreads();

    // qk[s,e] = sum_d q[s,d] * Wk[d,e]
    float k0 = 0.f, k1 = 0.f;
#pragma unroll 8
    for (int d = 0; d < 64; d++) {
        float qv = qm[s][d];
        k0 += qv * Wk[d * 64 + e0];
        k1 += qv * Wk[d * 64 + e1];
    }
    float qkg0 = k0 * g_in[e0], qkg1 = k1 * g_in[e1];
    float* qkgT = (float*)g_qkgT4;
    qkgT[(b * 64 + e0) * 8 + s] = qkg0;
    qkgT[(b * 64 + e1) * 8 + s] = qkg1;

    float c1 = qkg0 + qkg1;
    float c2 = k0 * b_in[e0] + k1 * b_in[e1];
#pragma unroll
    for (int off = 16; off; off >>= 1) {
        c1 += __shfl_xor_sync(0xffffffffu, c1, off);
        c2 += __shfl_xor_sync(0xffffffffu, c2, off);
    }
    if (lane == 0) { g_c1[b * 8 + s] = c1; g_c2[b * 8 + s] = c2; }
}

// ---------------- main streaming pass over x ----------------
__global__ __launch_bounds__(128) void k_main(const float* __restrict__ x) {
    int t = threadIdx.x;
    int tile = blockIdx.x, b = blockIdx.y;

    __shared__ float4 Xs4[CHUNK][16];     // 32 KB, quad-XOR swizzled
    __shared__ float  Ws[SS][CHUNK];      // 4 KB: attn*rstd weights
    __shared__ float4 qkg4[DD][2];        // 2 KB: qkgT[e][0..7]
    __shared__ float  c1s[SS], c2s[SS];
    __shared__ float  red[4][16];

    // load per-batch qkg / c1 / c2
    { int i = t; if (i < 128) ((float4*)qkg4)[i] = g_qkgT4[b * 128 + i]; }
    if (t < 8)       c1s[t]     = g_c1[b * 8 + t];
    else if (t < 16) c2s[t - 8] = g_c2[b * 8 + t - 8];

    float Aacc[8], Qacc[8];
#pragma unroll
    for (int s = 0; s < 8; s++) { Aacc[s] = 0.f; Qacc[s] = 0.f; }
    float4 pac = make_float4(0.f, 0.f, 0.f, 0.f);

    const float4* gx = (const float4*)(x + ((size_t)b * NN + (size_t)tile * ROWS_PB) * DD);

    for (int chunk = 0; chunk < ROWS_PB / CHUNK; ++chunk) {
        __syncthreads();   // previous phase-2 done; also covers qkg loads for chunk 0
        // ---- coalesced load 128 rows x 64 floats, swizzled store ----
#pragma unroll
        for (int i = 0; i < 16; i++) {
            int f4 = i * 128 + t;
            int r = f4 >> 4, q = f4 & 15;
            Xs4[r][q ^ (r & 15)] = gx[chunk * 2048 + f4];
        }
        __syncthreads();
        // ---- phase 1: per-row stats + logits + softmax ----
        {
            int r = t;
            int sw = r & 15;
            float d0 = 0, d1 = 0, d2 = 0, d3 = 0, d4 = 0, d5 = 0, d6 = 0, d7 = 0;
            float sm = 0.f, sq = 0.f;
#pragma unroll
            for (int qq = 0; qq < 16; qq++) {
                float4 xv = Xs4[r][qq ^ sw];
#pragma unroll
                for (int k = 0; k < 4; k++) {
                    float xe = (k == 0) ? xv.x : (k == 1) ? xv.y : (k == 2) ? xv.z : xv.w;
                    int e = 4 * qq + k;
                    float4 a0 = qkg4[e][0];
                    float4 a1 = qkg4[e][1];
                    sm += xe; sq += xe * xe;
                    d0 += xe * a0.x; d1 += xe * a0.y; d2 += xe * a0.z; d3 += xe * a0.w;
                    d4 += xe * a1.x; d5 += xe * a1.y; d6 += xe * a1.z; d7 += xe * a1.w;
                }
            }
            float mean = sm * (1.0f / 64.0f);
            float var  = sq * (1.0f / 64.0f) - mean * mean;
            float rstd = rsqrtf(var + LNEPS);
            float lg[8] = { d0, d1, d2, d3, d4, d5, d6, d7 };
            float mx = -1e30f;
#pragma unroll
            for (int s = 0; s < 8; s++) {
                lg[s] = rstd * (lg[s] - mean * c1s[s]) + c2s[s];
                mx = fmaxf(mx, lg[s]);
            }
            float es[8], ssum = 0.f;
#pragma unroll
            for (int s = 0; s < 8; s++) { es[s] = __expf(lg[s] - mx); ssum += es[s]; }
            float inv = 1.0f / ssum;
            float rm = rstd * mean;
#pragma unroll
            for (int s = 0; s < 8; s++) {
                float p = es[s] * inv;       // softmax
                Aacc[s] += p;
                float w = p * rstd;          // weight for P accumulation
                Qacc[s] += w * mean;
                Ws[s][r] = w;
            }
            (void)rm;
        }
        __syncthreads();
        // ---- phase 2: P[s][4q..4q+3] += sum_r Ws[s][r] * x[r][d] ----
        {
            int s = t >> 4, q = t & 15;
#pragma unroll 4
            for (int r = 0; r < CHUNK; r++) {
                float w = Ws[s][r];
                float4 xv = Xs4[r][q ^ (r & 15)];
                pac.x += w * xv.x; pac.y += w * xv.y;
                pac.z += w * xv.z; pac.w += w * xv.w;
            }
        }
    }
    // ---- write partials (deterministic, no atomics) ----
    {
        int s = t >> 4, q = t & 15;
        g_Pp4[((b * TILES + tile) * 8 + s) * 16 + q] = pac;
    }
#pragma unroll
    for (int s2 = 0; s2 < 8; s2++) {
        float a = Aacc[s2], qv = Qacc[s2];
#pragma unroll
        for (int off = 16; off; off >>= 1) {
            a  += __shfl_down_sync(0xffffffffu, a, off);
            qv += __shfl_down_sync(0xffffffffu, qv, off);
        }
        Aacc[s2] = a; Qacc[s2] = qv;
    }
    int w = t >> 5, lane = t & 31;
    if (lane == 0) {
#pragma unroll
        for (int s2 = 0; s2 < 8; s2++) { red[w][s2] = Aacc[s2]; red[w][8 + s2] = Qacc[s2]; }
    }
    __syncthreads();
    if (t < 16) {
        float v = red[0][t] + red[1][t] + red[2][t] + red[3][t];
        int base = (b * TILES + tile) * 8;
        if (t < 8) g_Ap[base + t] = v;
        else       g_Qp[base + t - 8] = v;
    }
}

// ---------------- finalize: updates -> GRU -> MLP -> new slots ----------------
__global__ __launch_bounds__(256) void k_finalize(
    const float* __restrict__ Wv,
    const float* __restrict__ W_ih, const float* __restrict__ W_hh,
    const float* __restrict__ b_ih, const float* __restrict__ b_hh,
    const float* __restrict__ W1, const float* __restrict__ b1,
    const float* __restrict__ W2, const float* __restrict__ b2,
    const float* __restrict__ g_in, const float* __restrict__ b_in,
    const float* __restrict__ g_mlp, const float* __restrict__ b_mlp,
    float* __restrict__ out, int last) {
    int b = blockIdx.x, t = threadIdx.x;
    __shared__ float Psh[512];   // reduced P, later reused as GRU hidden
    __shared__ float Avec[8], Qvec[8];
    __shared__ float prev[512];
    __shared__ float u[512];     // U vector, later reused as LN(hidden)
    __shared__ float upd[512];   // GRU input (attention updates)
    __shared__ float sl[64], sumv[64];
    __shared__ float h1[8 * HH];

    const float* Pp = (const float*)g_Pp4;
    for (int idx = t; idx < 512; idx += 256) {
        float acc = 0.f;
        for (int tl = 0; tl < TILES; tl++) acc += Pp[((size_t)(b * TILES + tl)) * 512 + idx];
        Psh[idx] = acc;
    }
    if (t < 8) {
        float a = 0.f;
        for (int tl = 0; tl < TILES; tl++) a += g_Ap[(b * TILES + tl) * 8 + t];
        Avec[t] = a;
    } else if (t < 16) {
        float q = 0.f;
        for (int tl = 0; tl < TILES; tl++) q += g_Qp[(b * TILES + tl) * 8 + (t - 8)];
        Qvec[t - 8] = q;
    }
    prev[t]       = g_slots[b * 512 + t];
    prev[t + 256] = g_slots[b * 512 + t + 256];
    __syncthreads();

    // SL[e] = sum_n lnx[n,e]  (uses softmax-sums-to-1 identity: PR = sum_s P)
    if (t < 64) {
        float pr = 0.f, qr = 0.f;
#pragma unroll
        for (int s = 0; s < 8; s++) { pr += Psh[s * 64 + t]; qr += Qvec[s]; }
        sl[t] = g_in[t] * (pr - qr) + b_in[t] * (float)NN;
    }
    __syncthreads();
    // sumv[d] = sum_n values[n,d]
    if (t < 64) {
        float sv = 0.f;
#pragma unroll 8
        for (int e = 0; e < 64; e++) sv += sl[e] * Wv[t * 64 + e];
        sumv[t] = sv;
    }
    // U[s,e] = sum_n attn * lnx
    {
        int s = t >> 5, e0 = (t & 31) * 2;
#pragma unroll
        for (int k = 0; k < 2; k++) {
            int e = e0 + k;
            u[s * 64 + e] = g_in[e] * (Psh[s * 64 + e] - Qvec[s]) + b_in[e] * Avec[s];
        }
    }
    __syncthreads();
    // updates[s,d] = (U@Wv^T + EPS*sumv) / (A + N*EPS)
    {
        int s = t >> 5, d0 = (t & 31) * 2;
        float zinv = 1.0f / (Avec[s] + (float)NN * EPSW);
#pragma unroll
        for (int k = 0; k < 2; k++) {
            int d = d0 + k;
            float raw = 0.f;
#pragma unroll 8
            for (int e = 0; e < 64; e++) raw += u[s * 64 + e] * Wv[d * 64 + e];
            upd[s * 64 + d] = (raw + EPSW * sumv[d]) * zinv;
        }
    }
    __syncthreads();
    // GRU cell
    {
        int s = t >> 5, d0 = (t & 31) * 2;
#pragma unroll
        for (int k = 0; k < 2; k++) {
            int d = d0 + k;
            float ir = b_ih[d], iz = b_ih[64 + d], in2 = b_ih[128 + d];
            float hr = b_hh[d], hz = b_hh[64 + d], hn = b_hh[128 + d];
#pragma unroll 4
            for (int e = 0; e < 64; e++) {
                float ue = upd[s * 64 + e], pe = prev[s * 64 + e];
                ir  += ue * W_ih[d * 64 + e];
                iz  += ue * W_ih[(64 + d) * 64 + e];
                in2 += ue * W_ih[(128 + d) * 64 + e];
                hr  += pe * W_hh[d * 64 + e];
                hz  += pe * W_hh[(64 + d) * 64 + e];
                hn  += pe * W_hh[(128 + d) * 64 + e];
            }
            float r = sigmoidf_(ir + hr);
            float z = sigmoidf_(iz + hz);
            float n = tanhf(in2 + r * hn);
            Psh[s * 64 + d] = (1.0f - z) * n + z * prev[s * 64 + d];  // hidden
        }
    }
    __syncthreads();
    // MLP layernorm (warp per s)
    {
        int s = t >> 5, lane = t & 31;
        int e0 = lane, e1 = lane + 32;
        float v0 = Psh[s * 64 + e0], v1 = Psh[s * 64 + e1];
        float sm = v0 + v1, sq = v0 * v0 + v1 * v1;
#pragma unroll
        for (int off = 16; off; off >>= 1) {
            sm += __shfl_xor_sync(0xffffffffu, sm, off);
            sq += __shfl_xor_sync(0xffffffffu, sq, off);
        }
        float mean = sm * (1.0f / 64.0f);
        float var  = sq * (1.0f / 64.0f) - mean * mean;
        float rstd = rsqrtf(var + LNEPS);
        u[s * 64 + e0] = (v0 - mean) * rstd * g_mlp[e0] + b_mlp[e0];
        u[s * 64 + e1] = (v1 - mean) * rstd * g_mlp[e1] + b_mlp[e1];
    }
    __syncthreads();
    // hidden layer
    {
        int s = t >> 5, j0 = (t & 31) * 4;
#pragma unroll
        for (int k = 0; k < 4; k++) {
            int j = j0 + k;
            float h = b1[j];
#pragma unroll 8
            for (int e = 0; e < 64; e++) h += u[s * 64 + e] * W1[j * 64 + e];
            h1[s * HH + j] = fmaxf(h, 0.0f);
        }
    }
    __syncthreads();
    // output + residual
    {
        int s = t >> 5, d0 = (t & 31) * 2;
#pragma unroll
        for (int k = 0; k < 2; k++) {
            int d = d0 + k;
            float o = Psh[s * 64 + d] + b2[d];
#pragma unroll 8
            for (int j = 0; j < HH; j++) o += h1[s * HH + j] * W2[d * HH + j];
            g_slots[b * 512 + s * 64 + d] = o;
            if (last) out[b * 512 + s * 64 + d] = o;
        }
    }
}

// ---------------- launch ----------------
extern "C" void kernel_launch(void* const* d_in, const int* in_sizes, int n_in,
                              void* d_out, int out_size) {
    const float* x        = (const float*)d_in[0];
    const float* noise    = (const float*)d_in[1];
    const float* mu       = (const float*)d_in[2];
    const float* lsig     = (const float*)d_in[3];
    const float* ln_in_g  = (const float*)d_in[4];
    const float* ln_in_b  = (const float*)d_in[5];
    const float* ln_sl_g  = (const float*)d_in[6];
    const float* ln_sl_b  = (const float*)d_in[7];
    const float* ln_ml_g  = (const float*)d_in[8];
    const float* ln_ml_b  = (const float*)d_in[9];
    const float* Wq       = (const float*)d_in[10];
    const float* Wk       = (const float*)d_in[11];
    const float* Wv       = (const float*)d_in[12];
    const float* W_ih     = (const float*)d_in[13];
    const float* W_hh     = (const float*)d_in[14];
    const float* b_ih     = (const float*)d_in[15];
    const float* b_hh     = (const float*)d_in[16];
    const float* W1       = (const float*)d_in[17];
    const float* b1       = (const float*)d_in[18];
    const float* W2       = (const float*)d_in[19];
    const float* b2       = (const float*)d_in[20];
    float* out = (float*)d_out;

    k_init<<<BB, 256>>>(noise, mu, lsig);
    for (int it = 0; it < 3; ++it) {
        k_qk<<<BB, 256>>>(Wq, Wk, ln_sl_g, ln_sl_b, ln_in_g, ln_in_b);
        dim3 grid(TILES, BB);
        k_main<<<grid, 128>>>(x);
        k_finalize<<<BB, 256>>>(Wv, W_ih, W_hh, b_ih, b_hh, W1, b1, W2, b2,
                                ln_in_g, ln_in_b, ln_ml_g, ln_ml_b, out, it == 2 ? 1 : 0);
    }
}

// round 2
// speedup vs baseline: 1.2867x; 1.2867x over previous
#include <cuda_runtime.h>
#include <math.h>

#define BB 32
#define NN 16384
#define SS 8
#define DD 64
#define HH 128
#define TILES 32
#define ROWS_PB 512   // rows per block = 4 chunks of 128
#define CHUNK 128
#define LNEPS 1e-5f
#define EPSW  1e-8f

// ---------------- device scratch (no allocations allowed) ----------------
__device__ float  g_slots[BB * SS * DD];           // current slots
__device__ float4 g_qkgT4[BB * DD * SS / 4];       // qkg transposed [b][e][s], s contiguous
__device__ float  g_c1[BB * SS];
__device__ float  g_c2[BB * SS];
__device__ float4 g_Pp4[BB * TILES * SS * DD / 4]; // per-tile partial P [b][tile][s][d]
__device__ float  g_Ap[BB * TILES * SS];           // partial sum softmax
__device__ float  g_Qp[BB * TILES * SS];           // partial sum softmax*rstd*mean

// transposed weights (e-major so output dim is lane-contiguous)
__device__ float  g_WihT[DD * 3 * DD];   // [e][row], row = gate*64+d  (12288)
__device__ float  g_WhhT[DD * 3 * DD];   // (12288)
__device__ float  g_W1T[DD * HH];        // [e][j]  (8192)
__device__ float  g_W2T[HH * DD];        // [j][d]  (8192)
__device__ float  g_WvT[DD * DD];        // [e][d]  (4096)

__device__ __forceinline__ float sigmoidf_(float x) { return 1.0f / (1.0f + expf(-x)); }

// ---------------- init: slots = mu + exp(log_sigma) * noise ----------------
__global__ void k_init(const float* __restrict__ noise, const float* __restrict__ mu,
                       const float* __restrict__ lsig) {
    int b = blockIdx.x, t = threadIdx.x;
    for (int idx = t; idx < SS * DD; idx += blockDim.x)
        g_slots[b * 512 + idx] = mu[idx] + expf(lsig[idx]) * noise[b * 512 + idx];
}

// ---------------- one-time weight transposes ----------------
__global__ void k_transpose(const float* __restrict__ W_ih, const float* __restrict__ W_hh,
                            const float* __restrict__ W1,   const float* __restrict__ W2,
                            const float* __restrict__ Wv) {
    int i = blockIdx.x * blockDim.x + threadIdx.x;
    if (i < 12288) {
        int e = i / 192, row = i % 192;
        g_WihT[i] = W_ih[row * 64 + e];
        g_WhhT[i] = W_hh[row * 64 + e];
    }
    if (i < 8192) {
        int e = i / 128, j = i % 128;
        g_W1T[i] = W1[j * 64 + e];
        int j2 = i / 64, d = i % 64;
        g_W2T[i] = W2[d * 128 + j2];
    }
    if (i < 4096) {
        int e = i / 64, d = i % 64;
        g_WvT[i] = Wv[d * 64 + e];
    }
}

// ---------------- per-iteration: q = LN(slots)@Wq^T * scale; qk = q@Wk; fold ln_in ----------------
__global__ void k_qk(const float* __restrict__ Wq, const float* __restrict__ Wk,
                     const float* __restrict__ g_slot, const float* __restrict__ b_slot,
                     const float* __restrict__ g_in, const float* __restrict__ b_in) {
    int b = blockIdx.x, t = threadIdx.x;
    int s = t >> 5, lane = t & 31;
    __shared__ float lns[SS][DD];
    __shared__ float qm[SS][DD];

    int e0 = lane, e1 = lane + 32;
    float v0 = g_slots[b * 512 + s * 64 + e0];
    float v1 = g_slots[b * 512 + s * 64 + e1];
    float sm = v0 + v1, sq = v0 * v0 + v1 * v1;
#pragma unroll
    for (int off = 16; off; off >>= 1) {
        sm += __shfl_xor_sync(0xffffffffu, sm, off);
        sq += __shfl_xor_sync(0xffffffffu, sq, off);
    }
    float mean = sm * (1.0f / 64.0f);
    float var  = sq * (1.0f / 64.0f) - mean * mean;
    float rstd = rsqrtf(var + LNEPS);
    lns[s][e0] = (v0 - mean) * rstd * g_slot[e0] + b_slot[e0];
    lns[s][e1] = (v1 - mean) * rstd * g_slot[e1] + b_slot[e1];
    __syncthreads();

    // q[s,d] = scale * sum_e lns[s,e] * Wq[d,e]   (d = lane, lane+32)
    float q0 = 0.f, q1 = 0.f;
#pragma unroll 8
    for (int e = 0; e < 64; e++) {
        float l = lns[s][e];
        q0 += l * Wq[e0 * 64 + e];
        q1 += l * Wq[e1 * 64 + e];
    }
    qm[s][e0] = q0 * 0.125f;   // D^-0.5 = 1/8
    qm[s][e1] = q1 * 0.125f;
    __syncthreads();

    // qk[s,e] = sum_d q[s,d] * Wk[d,e]
    float k0 = 0.f, k1 = 0.f;
#pragma unroll 8
    for (int d = 0; d < 64; d++) {
        float qv = qm[s][d];
        k0 += qv * Wk[d * 64 + e0];
        k1 += qv * Wk[d * 64 + e1];
    }
    float qkg0 = k0 * g_in[e0], qkg1 = k1 * g_in[e1];
    float* qkgT = (float*)g_qkgT4;
    qkgT[(b * 64 + e0) * 8 + s] = qkg0;
    qkgT[(b * 64 + e1) * 8 + s] = qkg1;

    float c1 = qkg0 + qkg1;
    float c2 = k0 * b_in[e0] + k1 * b_in[e1];
#pragma unroll
    for (int off = 16; off; off >>= 1) {
        c1 += __shfl_xor_sync(0xffffffffu, c1, off);
        c2 += __shfl_xor_sync(0xffffffffu, c2, off);
    }
    if (lane == 0) { g_c1[b * 8 + s] = c1; g_c2[b * 8 + s] = c2; }
}

// ---------------- main streaming pass over x ----------------
__global__ __launch_bounds__(128) void k_main(const float* __restrict__ x) {
    int t = threadIdx.x;
    int tile = blockIdx.x, b = blockIdx.y;

    __shared__ float4 Xs4[CHUNK][16];     // 32 KB, quad-XOR swizzled
    __shared__ float  Ws[SS][CHUNK];      // 4 KB: attn*rstd weights
    __shared__ float4 qkg4[DD][2];        // 2 KB: qkgT[e][0..7]
    __shared__ float  c1s[SS], c2s[SS];
    __shared__ float  red[4][16];

    // load per-batch qkg / c1 / c2
    { int i = t; if (i < 128) ((float4*)qkg4)[i] = g_qkgT4[b * 128 + i]; }
    if (t < 8)       c1s[t]     = g_c1[b * 8 + t];
    else if (t < 16) c2s[t - 8] = g_c2[b * 8 + t - 8];

    float Aacc[8], Qacc[8];
#pragma unroll
    for (int s = 0; s < 8; s++) { Aacc[s] = 0.f; Qacc[s] = 0.f; }
    float4 pac = make_float4(0.f, 0.f, 0.f, 0.f);

    const float4* gx = (const float4*)(x + ((size_t)b * NN + (size_t)tile * ROWS_PB) * DD);

    for (int chunk = 0; chunk < ROWS_PB / CHUNK; ++chunk) {
        __syncthreads();   // previous phase-2 done; also covers qkg loads for chunk 0
        // ---- coalesced load 128 rows x 64 floats, swizzled store ----
#pragma unroll
        for (int i = 0; i < 16; i++) {
            int f4 = i * 128 + t;
            int r = f4 >> 4, q = f4 & 15;
            Xs4[r][q ^ (r & 15)] = gx[chunk * 2048 + f4];
        }
        __syncthreads();
        // ---- phase 1: per-row stats + logits + softmax ----
        {
            int r = t;
            int sw = r & 15;
            float d0 = 0, d1 = 0, d2 = 0, d3 = 0, d4 = 0, d5 = 0, d6 = 0, d7 = 0;
            float sm = 0.f, sq = 0.f;
#pragma unroll
            for (int qq = 0; qq < 16; qq++) {
                float4 xv = Xs4[r][qq ^ sw];
#pragma unroll
                for (int k = 0; k < 4; k++) {
                    float xe = (k == 0) ? xv.x : (k == 1) ? xv.y : (k == 2) ? xv.z : xv.w;
                    int e = 4 * qq + k;
                    float4 a0 = qkg4[e][0];
                    float4 a1 = qkg4[e][1];
                    sm += xe; sq += xe * xe;
                    d0 += xe * a0.x; d1 += xe * a0.y; d2 += xe * a0.z; d3 += xe * a0.w;
                    d4 += xe * a1.x; d5 += xe * a1.y; d6 += xe * a1.z; d7 += xe * a1.w;
                }
            }
            float mean = sm * (1.0f / 64.0f);
            float var  = sq * (1.0f / 64.0f) - mean * mean;
            float rstd = rsqrtf(var + LNEPS);
            float lg[8] = { d0, d1, d2, d3, d4, d5, d6, d7 };
            float mx = -1e30f;
#pragma unroll
            for (int s = 0; s < 8; s++) {
                lg[s] = rstd * (lg[s] - mean * c1s[s]) + c2s[s];
                mx = fmaxf(mx, lg[s]);
            }
            float es[8], ssum = 0.f;
#pragma unroll
            for (int s = 0; s < 8; s++) { es[s] = __expf(lg[s] - mx); ssum += es[s]; }
            float inv = 1.0f / ssum;
#pragma unroll
            for (int s = 0; s < 8; s++) {
                float p = es[s] * inv;       // softmax
                Aacc[s] += p;
                float w = p * rstd;          // weight for P accumulation
                Qacc[s] += w * mean;
                Ws[s][r] = w;
            }
        }
        __syncthreads();
        // ---- phase 2: P[s][4q..4q+3] += sum_r Ws[s][r] * x[r][d] ----
        {
            int s = t >> 4, q = t & 15;
#pragma unroll 4
            for (int r = 0; r < CHUNK; r++) {
                float w = Ws[s][r];
                float4 xv = Xs4[r][q ^ (r & 15)];
                pac.x += w * xv.x; pac.y += w * xv.y;
                pac.z += w * xv.z; pac.w += w * xv.w;
            }
        }
    }
    // ---- write partials (deterministic, no atomics) ----
    {
        int s = t >> 4, q = t & 15;
        g_Pp4[((b * TILES + tile) * 8 + s) * 16 + q] = pac;
    }
#pragma unroll
    for (int s2 = 0; s2 < 8; s2++) {
        float a = Aacc[s2], qv = Qacc[s2];
#pragma unroll
        for (int off = 16; off; off >>= 1) {
            a  += __shfl_down_sync(0xffffffffu, a, off);
            qv += __shfl_down_sync(0xffffffffu, qv, off);
        }
        Aacc[s2] = a; Qacc[s2] = qv;
    }
    int w = t >> 5, lane = t & 31;
    if (lane == 0) {
#pragma unroll
        for (int s2 = 0; s2 < 8; s2++) { red[w][s2] = Aacc[s2]; red[w][8 + s2] = Qacc[s2]; }
    }
    __syncthreads();
    if (t < 16) {
        float v = red[0][t] + red[1][t] + red[2][t] + red[3][t];
        int base = (b * TILES + tile) * 8;
        if (t < 8) g_Ap[base + t] = v;
        else       g_Qp[base + t - 8] = v;
    }
}

// ---------------- finalize: updates -> GRU -> MLP -> new slots ----------------
// 512 threads: one thread per (s, d) output; all weight loads lane-contiguous.
__global__ __launch_bounds__(512) void k_finalize(
    const float* __restrict__ b_ih, const float* __restrict__ b_hh,
    const float* __restrict__ b1,   const float* __restrict__ b2,
    const float* __restrict__ g_in, const float* __restrict__ b_in,
    const float* __restrict__ g_mlp, const float* __restrict__ b_mlp,
    float* __restrict__ out, int last) {
    int b = blockIdx.x, t = threadIdx.x;
    int s = t >> 6, d = t & 63;

    __shared__ float Psh[512];    // reduced P; later reused as GRU hidden
    __shared__ float Avec[8], Qvec[8];
    __shared__ float prev[512];
    __shared__ float u[512];      // U vector; later reused as LN(hidden)
    __shared__ float upd[512];    // GRU input (attention updates)
    __shared__ float sl[64], sumv[64];
    __shared__ float h1[SS * HH];

    // ---- reduce per-tile partials ----
    {
        const float* Pp = (const float*)g_Pp4;
        float acc = 0.f;
#pragma unroll 8
        for (int tl = 0; tl < TILES; tl++) acc += Pp[((size_t)(b * TILES + tl)) * 512 + t];
        Psh[t] = acc;
    }
    if (t < 8) {
        float a = 0.f;
#pragma unroll 8
        for (int tl = 0; tl < TILES; tl++) a += g_Ap[(b * TILES + tl) * 8 + t];
        Avec[t] = a;
    } else if (t < 16) {
        float q = 0.f;
#pragma unroll 8
        for (int tl = 0; tl < TILES; tl++) q += g_Qp[(b * TILES + tl) * 8 + (t - 8)];
        Qvec[t - 8] = q;
    }
    prev[t] = g_slots[b * 512 + t];
    __syncthreads();

    // SL[e] = sum_n lnx[n,e]; U[s,e] = sum_n attn*lnx
    if (t < 64) {
        float pr = 0.f, qr = 0.f;
#pragma unroll
        for (int s2 = 0; s2 < 8; s2++) { pr += Psh[s2 * 64 + t]; qr += Qvec[s2]; }
        sl[t] = g_in[t] * (pr - qr) + b_in[t] * (float)NN;
    }
    u[t] = g_in[d] * (Psh[t] - Qvec[s]) + b_in[d] * Avec[s];
    __syncthreads();

    // sumv[d] = sum_n values[n,d] = SL @ WvT
    if (t < 64) {
        float sv = 0.f;
#pragma unroll 8
        for (int e = 0; e < 64; e++) sv += sl[e] * g_WvT[e * 64 + t];
        sumv[t] = sv;
    }
    __syncthreads();

    // updates[s,d] = (U @ Wv^T + EPS*sumv) / (A + N*EPS)
    {
        float zinv = 1.0f / (Avec[s] + (float)NN * EPSW);
        float raw = 0.f;
#pragma unroll 8
        for (int e = 0; e < 64; e++) raw += u[s * 64 + e] * g_WvT[e * 64 + d];
        upd[t] = (raw + EPSW * sumv[d]) * zinv;
    }
    __syncthreads();

    // GRU cell — coalesced transposed weights, lane = d
    {
        float ir = b_ih[d], iz = b_ih[64 + d], in2 = b_ih[128 + d];
        float hr = b_hh[d], hz = b_hh[64 + d], hn = b_hh[128 + d];
#pragma unroll 4
        for (int e = 0; e < 64; e++) {
            float ue = upd[s * 64 + e], pe = prev[s * 64 + e];
            const float* wi = &g_WihT[e * 192];
            const float* wh = &g_WhhT[e * 192];
            ir  += ue * wi[d];       iz  += ue * wi[64 + d];  in2 += ue * wi[128 + d];
            hr  += pe * wh[d];       hz  += pe * wh[64 + d];  hn  += pe * wh[128 + d];
        }
        float r = sigmoidf_(ir + hr);
        float z = sigmoidf_(iz + hz);
        float n = tanhf(in2 + r * hn);
        float hid = (1.0f - z) * n + z * prev[t];
        __syncthreads();
        Psh[t] = hid;     // hidden
    }
    __syncthreads();

    // MLP layernorm (first 8 warps, one warp per s)
    if (t < 256) {
        int s2 = t >> 5, lane = t & 31;
        int e0 = lane, e1 = lane + 32;
        float v0 = Psh[s2 * 64 + e0], v1 = Psh[s2 * 64 + e1];
        float sm = v0 + v1, sq = v0 * v0 + v1 * v1;
#pragma unroll
        for (int off = 16; off; off >>= 1) {
            sm += __shfl_xor_sync(0xffffffffu, sm, off);
            sq += __shfl_xor_sync(0xffffffffu, sq, off);
        }
        float mean = sm * (1.0f / 64.0f);
        float var  = sq * (1.0f / 64.0f) - mean * mean;
        float rstd = rsqrtf(var + LNEPS);
        u[s2 * 64 + e0] = (v0 - mean) * rstd * g_mlp[e0] + b_mlp[e0];
        u[s2 * 64 + e1] = (v1 - mean) * rstd * g_mlp[e1] + b_mlp[e1];
    }
    __syncthreads();

    // hidden layer: thread handles j = d and j = d+64
    {
        float h0 = b1[d], h64 = b1[d + 64];
#pragma unroll 8
        for (int e = 0; e < 64; e++) {
            float ue = u[s * 64 + e];
            h0  += ue * g_W1T[e * 128 + d];
            h64 += ue * g_W1T[e * 128 + 64 + d];
        }
        h1[s * HH + d]      = fmaxf(h0, 0.0f);
        h1[s * HH + 64 + d] = fmaxf(h64, 0.0f);
    }
    __syncthreads();

    // output + residual
    {
        float o = Psh[t] + b2[d];
#pragma unroll 8
        for (int j = 0; j < HH; j++) o += h1[s * HH + j] * g_W2T[j * 64 + d];
        g_slots[b * 512 + t] = o;
        if (last) out[b * 512 + t] = o;
    }
}

// ---------------- launch ----------------
extern "C" void kernel_launch(void* const* d_in, const int* in_sizes, int n_in,
                              void* d_out, int out_size) {
    const float* x        = (const float*)d_in[0];
    const float* noise    = (const float*)d_in[1];
    const float* mu       = (const float*)d_in[2];
    const float* lsig     = (const float*)d_in[3];
    const float* ln_in_g  = (const float*)d_in[4];
    const float* ln_in_b  = (const float*)d_in[5];
    const float* ln_sl_g  = (const float*)d_in[6];
    const float* ln_sl_b  = (const float*)d_in[7];
    const float* ln_ml_g  = (const float*)d_in[8];
    const float* ln_ml_b  = (const float*)d_in[9];
    const float* Wq       = (const float*)d_in[10];
    const float* Wk       = (const float*)d_in[11];
    const float* Wv       = (const float*)d_in[12];
    const float* W_ih     = (const float*)d_in[13];
    const float* W_hh     = (const float*)d_in[14];
    const float* b_ih     = (const float*)d_in[15];
    const float* b_hh     = (const float*)d_in[16];
    const float* W1       = (const float*)d_in[17];
    const float* b1       = (const float*)d_in[18];
    const float* W2       = (const float*)d_in[19];
    const float* b2       = (const float*)d_in[20];
    float* out = (float*)d_out;

    k_init<<<BB, 256>>>(noise, mu, lsig);
    k_transpose<<<48, 256>>>(W_ih, W_hh, W1, W2, Wv);
    for (int it = 0; it < 3; ++it) {
        k_qk<<<BB, 256>>>(Wq, Wk, ln_sl_g, ln_sl_b, ln_in_g, ln_in_b);
        dim3 grid(TILES, BB);
        k_main<<<grid, 128>>>(x);
        k_finalize<<<BB, 512>>>(b_ih, b_hh, b1, b2,
                                ln_in_g, ln_in_b, ln_ml_g, ln_ml_b, out, it == 2 ? 1 : 0);
    }
}

// round 6
// speedup vs baseline: 1.9591x; 1.5225x over previous
#include <cuda_runtime.h>
#include <math.h>

#define BB 32
#define NN 16384
#define SS 8
#define DD 64
#define HH 128
#define TILES 32
#define ROWS_PB 512    // rows per block = 2 chunks of 256
#define CHUNK 256
#define LNEPS 1e-5f
#define EPSW  1e-8f

typedef unsigned long long u64;

// dynamic smem carve (bytes)
#define XS_OFF   0
#define XS_BYTES (CHUNK * 16 * 16)          // 65536: float4 Xs[256][16]
#define WS_OFF   (XS_OFF + XS_BYTES)        // 65536
#define WS_BYTES (CHUNK * 32)               // 8192: ulonglong2 Ws2[256][2]
#define QP_OFF   (WS_OFF + WS_BYTES)        // 73728
#define QP_BYTES (DD * SS * 8)              // 4096: u64 qkgP[64][8] (splatted)
#define MS_OFF   (QP_OFF + QP_BYTES)        // 77824
#define MS_BYTES 512
#define SMEM_K_MAIN (MS_OFF + MS_BYTES)     // 78336

// ---------------- device scratch ----------------
__device__ float  g_slots[BB * SS * DD];
__device__ float4 g_qkgT4[BB * DD * SS / 4];       // [b][e][s], s contiguous
__device__ float  g_c1[BB * SS];
__device__ float  g_c2[BB * SS];
__device__ float4 g_Pp4[BB * TILES * SS * DD / 4];
__device__ float  g_Ap[BB * TILES * SS];
__device__ float  g_Qp[BB * TILES * SS];

// transposed weights (e-major so output dim is lane-contiguous)
__device__ float  g_WihT[DD * 3 * DD];
__device__ float  g_WhhT[DD * 3 * DD];
__device__ float  g_W1T[DD * HH];
__device__ float  g_W2T[HH * DD];
__device__ float  g_WvT[DD * DD];
__device__ float  g_WqT[DD * DD];

__device__ __forceinline__ float sigmoidf_(float x) { return 1.0f / (1.0f + expf(-x)); }

// ---- f32x2 packed helpers ----
__device__ __forceinline__ u64 pk2(float lo, float hi) {
    u64 r;
    asm("mov.b64 %0, {%1, %2};" : "=l"(r) : "r"(__float_as_uint(lo)), "r"(__float_as_uint(hi)));
    return r;
}
__device__ __forceinline__ void upk2(u64 v, float& lo, float& hi) {
    unsigned a, b;
    asm("mov.b64 {%0, %1}, %2;" : "=r"(a), "=r"(b) : "l"(v));
    lo = __uint_as_float(a); hi = __uint_as_float(b);
}
__device__ __forceinline__ u64 ffma2_(u64 a, u64 b, u64 c) {
    u64 d;
    asm("fma.rn.f32x2 %0, %1, %2, %3;" : "=l"(d) : "l"(a), "l"(b), "l"(c));
    return d;
}
__device__ __forceinline__ u64 fadd2_(u64 a, u64 b) {
    u64 d;
    asm("add.rn.f32x2 %0, %1, %2;" : "=l"(d) : "l"(a), "l"(b));
    return d;
}

// ---------------- init ----------------
__global__ void k_init(const float* __restrict__ noise, const float* __restrict__ mu,
                       const float* __restrict__ lsig) {
    int b = blockIdx.x, t = threadIdx.x;
    for (int idx = t; idx < SS * DD; idx += blockDim.x)
        g_slots[b * 512 + idx] = mu[idx] + expf(lsig[idx]) * noise[b * 512 + idx];
}

// ---------------- one-time weight transposes ----------------
__global__ void k_transpose(const float* __restrict__ W_ih, const float* __restrict__ W_hh,
                            const float* __restrict__ W1,   const float* __restrict__ W2,
                            const float* __restrict__ Wv,   const float* __restrict__ Wq) {
    int i = blockIdx.x * blockDim.x + threadIdx.x;
    if (i < 12288) {
        int e = i / 192, row = i % 192;
        g_WihT[i] = W_ih[row * 64 + e];
        g_WhhT[i] = W_hh[row * 64 + e];
    }
    if (i < 8192) {
        int e = i / 128, j = i % 128;
        g_W1T[i] = W1[j * 64 + e];
        int j2 = i / 64, d = i % 64;
        g_W2T[i] = W2[d * 128 + j2];
    }
    if (i < 4096) {
        int e = i / 64, d = i % 64;
        g_WvT[i] = Wv[d * 64 + e];
        g_WqT[i] = Wq[d * 64 + e];
    }
}

// ---------------- per-iteration qk fold ----------------
__global__ void k_qk(const float* __restrict__ Wk,
                     const float* __restrict__ g_slot, const float* __restrict__ b_slot,
                     const float* __restrict__ g_in, const float* __restrict__ b_in) {
    int b = blockIdx.x, t = threadIdx.x;
    int s = t >> 5, lane = t & 31;
    __shared__ float lns[SS][DD];
    __shared__ float qm[SS][DD];

    int e0 = lane, e1 = lane + 32;
    float v0 = g_slots[b * 512 + s * 64 + e0];
    float v1 = g_slots[b * 512 + s * 64 + e1];
    float sm = v0 + v1, sq = v0 * v0 + v1 * v1;
#pragma unroll
    for (int off = 16; off; off >>= 1) {
        sm += __shfl_xor_sync(0xffffffffu, sm, off);
        sq += __shfl_xor_sync(0xffffffffu, sq, off);
    }
    float mean = sm * (1.0f / 64.0f);
    float var  = sq * (1.0f / 64.0f) - mean * mean;
    float rstd = rsqrtf(var + LNEPS);
    lns[s][e0] = (v0 - mean) * rstd * g_slot[e0] + b_slot[e0];
    lns[s][e1] = (v1 - mean) * rstd * g_slot[e1] + b_slot[e1];
    __syncthreads();

    // q[s,d] = scale * sum_e lns[s,e] * WqT[e,d]   (coalesced: lane = d)
    float q0 = 0.f, q1 = 0.f;
#pragma unroll 8
    for (int e = 0; e < 64; e++) {
        float l = lns[s][e];
        q0 += l * g_WqT[e * 64 + e0];
        q1 += l * g_WqT[e * 64 + e1];
    }
    qm[s][e0] = q0 * 0.125f;
    qm[s][e1] = q1 * 0.125f;
    __syncthreads();

    // qk[s,e] = sum_d q[s,d] * Wk[d,e]   (coalesced: lane = e)
    float k0 = 0.f, k1 = 0.f;
#pragma unroll 8
    for (int d = 0; d < 64; d++) {
        float qv = qm[s][d];
        k0 += qv * Wk[d * 64 + e0];
        k1 += qv * Wk[d * 64 + e1];
    }
    float qkg0 = k0 * g_in[e0], qkg1 = k1 * g_in[e1];
    float* qkgT = (float*)g_qkgT4;
    qkgT[(b * 64 + e0) * 8 + s] = qkg0;
    qkgT[(b * 64 + e1) * 8 + s] = qkg1;

    float c1 = qkg0 + qkg1;
    float c2 = k0 * b_in[e0] + k1 * b_in[e1];
#pragma unroll
    for (int off = 16; off; off >>= 1) {
        c1 += __shfl_xor_sync(0xffffffffu, c1, off);
        c2 += __shfl_xor_sync(0xffffffffu, c2, off);
    }
    if (lane == 0) { g_c1[b * 8 + s] = c1; g_c2[b * 8 + s] = c2; }
}

// ---------------- main streaming pass ----------------
__global__ __launch_bounds__(128) void k_main(const float* __restrict__ x) {
    extern __shared__ char smem[];
    float4*     Xs4  = (float4*)(smem + XS_OFF);      // [256][16] swizzled
    ulonglong2* Ws2  = (ulonglong2*)(smem + WS_OFF);  // [256][2]: packed slot-pair weights
    u64*        qkgP = (u64*)(smem + QP_OFF);         // [64][8] splatted (v,v)
    float*      c1s  = (float*)(smem + MS_OFF);       // 8
    float*      c2s  = c1s + 8;                       // 8
    float*      red  = c2s + 8;                       // [4][16]

    int t = threadIdx.x;
    int tile = blockIdx.x, b = blockIdx.y;

    // build splatted qkg table + consts
    {
        const float* qkgT = (const float*)g_qkgT4;
#pragma unroll
        for (int k = 0; k < 4; k++) {
            int idx = t * 4 + k;
            float v = qkgT[b * 512 + idx];
            qkgP[idx] = pk2(v, v);
        }
    }
    if (t < 8)       c1s[t]     = g_c1[b * 8 + t];
    else if (t < 16) c2s[t - 8] = g_c2[b * 8 + t - 8];

    float Aacc[8], Qacc[8];
#pragma unroll
    for (int s = 0; s < 8; s++) { Aacc[s] = 0.f; Qacc[s] = 0.f; }
    u64 acc[16];   // [sp][j]: packed (P[2sp][4q+j], P[2sp+1][4q+j])
#pragma unroll
    for (int i = 0; i < 16; i++) acc[i] = 0ull;

    const float4* gx = (const float4*)(x + ((size_t)b * NN + (size_t)tile * ROWS_PB) * DD);
    int sub = t >> 4, q = t & 15;
    int sw = t & 15;

    __syncthreads();

    for (int chunk = 0; chunk < ROWS_PB / CHUNK; ++chunk) {
        if (chunk) __syncthreads();
        // ---- load 256 rows x 64 floats, swizzled ----
#pragma unroll
        for (int i = 0; i < 32; i++) {
            int f4 = i * 128 + t;
            int r = f4 >> 4, qq = f4 & 15;
            Xs4[r * 16 + (qq ^ (r & 15))] = gx[chunk * 4096 + f4];
        }
        __syncthreads();

        // ---- phase 1: rows t and t+128, packed f32x2 ----
        {
            u64 lg2[8];
#pragma unroll
            for (int s = 0; s < 8; s++) lg2[s] = 0ull;
            u64 sum2 = 0ull, sq2 = 0ull;
#pragma unroll
            for (int qq = 0; qq < 16; qq++) {
                float4 xa = Xs4[t * 16 + (qq ^ sw)];
                float4 xb = Xs4[(t + 128) * 16 + (qq ^ sw)];
#pragma unroll
                for (int k = 0; k < 4; k++) {
                    float ea = (k == 0) ? xa.x : (k == 1) ? xa.y : (k == 2) ? xa.z : xa.w;
                    float eb = (k == 0) ? xb.x : (k == 1) ? xb.y : (k == 2) ? xb.z : xb.w;
                    u64 xab = pk2(ea, eb);
                    const ulonglong2* qp = (const ulonglong2*)(qkgP + (qq * 4 + k) * 8);
                    ulonglong2 q01 = qp[0], q23 = qp[1], q45 = qp[2], q67 = qp[3];
                    lg2[0] = ffma2_(xab, q01.x, lg2[0]);
                    lg2[1] = ffma2_(xab, q01.y, lg2[1]);
                    lg2[2] = ffma2_(xab, q23.x, lg2[2]);
                    lg2[3] = ffma2_(xab, q23.y, lg2[3]);
                    lg2[4] = ffma2_(xab, q45.x, lg2[4]);
                    lg2[5] = ffma2_(xab, q45.y, lg2[5]);
                    lg2[6] = ffma2_(xab, q67.x, lg2[6]);
                    lg2[7] = ffma2_(xab, q67.y, lg2[7]);
                    sum2 = fadd2_(sum2, xab);
                    sq2  = ffma2_(xab, xab, sq2);
                }
            }
            float sA, sB, sqA, sqB;
            upk2(sum2, sA, sB); upk2(sq2, sqA, sqB);
            float lgA[8], lgB[8];
#pragma unroll
            for (int s = 0; s < 8; s++) upk2(lg2[s], lgA[s], lgB[s]);

#pragma unroll
            for (int rr = 0; rr < 2; rr++) {
                float smv  = rr ? sB : sA;
                float sqv  = rr ? sqB : sqA;
                float* lg  = rr ? lgB : lgA;
                int row    = rr ? (t + 128) : t;
                float mean = smv * (1.0f / 64.0f);
                float var  = sqv * (1.0f / 64.0f) - mean * mean;
                float rstd = rsqrtf(var + LNEPS);
                float mx = -1e30f;
#pragma unroll
                for (int s = 0; s < 8; s++) {
                    lg[s] = rstd * (lg[s] - mean * c1s[s]) + c2s[s];
                    mx = fmaxf(mx, lg[s]);
                }
                float es[8], ssum = 0.f;
#pragma unroll
                for (int s = 0; s < 8; s++) { es[s] = __expf(lg[s] - mx); ssum += es[s]; }
                float inv = 1.0f / ssum;
                float w[8];
#pragma unroll
                for (int s = 0; s < 8; s++) {
                    float p = es[s] * inv;
                    Aacc[s] += p;
                    w[s] = p * rstd;
                    Qacc[s] += w[s] * mean;
                }
                ulonglong2 v0, v1;
                v0.x = pk2(w[0], w[1]); v0.y = pk2(w[2], w[3]);
                v1.x = pk2(w[4], w[5]); v1.y = pk2(w[6], w[7]);
                Ws2[row * 2 + 0] = v0;
                Ws2[row * 2 + 1] = v1;
            }
        }
        __syncthreads();

        // ---- phase 2: thread (sub, q) accumulates all 8 slots over 32 rows ----
        {
            int rbase = sub * 32;
#pragma unroll 4
            for (int i = 0; i < 32; i++) {
                int r = rbase + i;
                ulonglong2 wA = Ws2[r * 2 + 0];   // (w0,w1),(w2,w3)
                ulonglong2 wB = Ws2[r * 2 + 1];   // (w4,w5),(w6,w7)
                float4 xv = Xs4[r * 16 + (q ^ (r & 15))];
                u64 x0 = pk2(xv.x, xv.x), x1 = pk2(xv.y, xv.y);
                u64 x2 = pk2(xv.z, xv.z), x3 = pk2(xv.w, xv.w);
                acc[0]  = ffma2_(wA.x, x0, acc[0]);
                acc[1]  = ffma2_(wA.x, x1, acc[1]);
                acc[2]  = ffma2_(wA.x, x2, acc[2]);
                acc[3]  = ffma2_(wA.x, x3, acc[3]);
                acc[4]  = ffma2_(wA.y, x0, acc[4]);
                acc[5]  = ffma2_(wA.y, x1, acc[5]);
                acc[6]  = ffma2_(wA.y, x2, acc[6]);
                acc[7]  = ffma2_(wA.y, x3, acc[7]);
                acc[8]  = ffma2_(wB.x, x0, acc[8]);
                acc[9]  = ffma2_(wB.x, x1, acc[9]);
                acc[10] = ffma2_(wB.x, x2, acc[10]);
                acc[11] = ffma2_(wB.x, x3, acc[11]);
                acc[12] = ffma2_(wB.y, x0, acc[12]);
                acc[13] = ffma2_(wB.y, x1, acc[13]);
                acc[14] = ffma2_(wB.y, x2, acc[14]);
                acc[15] = ffma2_(wB.y, x3, acc[15]);
            }
        }
    }

    // ---- reduce sub-partials for P (alias Xs region) ----
    __syncthreads();
    float* Pred = (float*)(smem + XS_OFF);   // [8 sub][8 s][64 d]
#pragma unroll
    for (int sp = 0; sp < 4; sp++) {
#pragma unroll
        for (int j = 0; j < 4; j++) {
            float lo, hi;
            upk2(acc[sp * 4 + j], lo, hi);
            Pred[(sub * 8 + 2 * sp) * 64 + 4 * q + j]     = lo;
            Pred[(sub * 8 + 2 * sp + 1) * 64 + 4 * q + j] = hi;
        }
    }
    __syncthreads();
    {
        int s = t >> 4, qq = t & 15;
        float4 r4 = make_float4(0.f, 0.f, 0.f, 0.f);
#pragma unroll
        for (int sb = 0; sb < 8; sb++) {
            float4 v = ((float4*)Pred)[(sb * 8 + s) * 16 + qq];
            r4.x += v.x; r4.y += v.y; r4.z += v.z; r4.w += v.w;
        }
        g_Pp4[((b * TILES + tile) * 8 + s) * 16 + qq] = r4;
    }

    // ---- A/Q reduction ----
#pragma unroll
    for (int s2 = 0; s2 < 8; s2++) {
        float a = Aacc[s2], qv = Qacc[s2];
#pragma unroll
        for (int off = 16; off; off >>= 1) {
            a  += __shfl_down_sync(0xffffffffu, a, off);
            qv += __shfl_down_sync(0xffffffffu, qv, off);
        }
        Aacc[s2] = a; Qacc[s2] = qv;
    }
    int w = t >> 5, lane = t & 31;
    if (lane == 0) {
#pragma unroll
        for (int s2 = 0; s2 < 8; s2++) { red[w * 16 + s2] = Aacc[s2]; red[w * 16 + 8 + s2] = Qacc[s2]; }
    }
    __syncthreads();
    if (t < 16) {
        float v = red[0 * 16 + t] + red[1 * 16 + t] + red[2 * 16 + t] + red[3 * 16 + t];
        int base = (b * TILES + tile) * 8;
        if (t < 8) g_Ap[base + t] = v;
        else       g_Qp[base + t - 8] = v;
    }
}

// ---------------- finalize ----------------
__global__ __launch_bounds__(512) void k_finalize(
    const float* __restrict__ b_ih, const float* __restrict__ b_hh,
    const float* __restrict__ b1,   const float* __restrict__ b2,
    const float* __restrict__ g_in, const float* __restrict__ b_in,
    const float* __restrict__ g_mlp, const float* __restrict__ b_mlp,
    float* __restrict__ out, int last) {
    int b = blockIdx.x, t = threadIdx.x;
    int s = t >> 6, d = t & 63;

    __shared__ float Psh[512];
    __shared__ float Avec[8], Qvec[8];
    __shared__ float prev[512];
    __shared__ float u[512];
    __shared__ float upd[512];
    __shared__ float sl[64], sumv[64];
    __shared__ float h1[SS * HH];

    {
        const float* Pp = (const float*)g_Pp4;
        float acc = 0.f;
#pragma unroll 8
        for (int tl = 0; tl < TILES; tl++) acc += Pp[((size_t)(b * TILES + tl)) * 512 + t];
        Psh[t] = acc;
    }
    if (t < 8) {
        float a = 0.f;
#pragma unroll 8
        for (int tl = 0; tl < TILES; tl++) a += g_Ap[(b * TILES + tl) * 8 + t];
        Avec[t] = a;
    } else if (t < 16) {
        float qv = 0.f;
#pragma unroll 8
        for (int tl = 0; tl < TILES; tl++) qv += g_Qp[(b * TILES + tl) * 8 + (t - 8)];
        Qvec[t - 8] = qv;
    }
    prev[t] = g_slots[b * 512 + t];
    __syncthreads();

    if (t < 64) {
        float pr = 0.f, qr = 0.f;
#pragma unroll
        for (int s2 = 0; s2 < 8; s2++) { pr += Psh[s2 * 64 + t]; qr += Qvec[s2]; }
        sl[t] = g_in[t] * (pr - qr) + b_in[t] * (float)NN;
    }
    u[t] = g_in[d] * (Psh[t] - Qvec[s]) + b_in[d] * Avec[s];
    __syncthreads();

    if (t < 64) {
        float sv = 0.f;
#pragma unroll 8
        for (int e = 0; e < 64; e++) sv += sl[e] * g_WvT[e * 64 + t];
        sumv[t] = sv;
    }
    __syncthreads();

    {
        float zinv = 1.0f / (Avec[s] + (float)NN * EPSW);
        float raw = 0.f;
#pragma unroll 8
        for (int e = 0; e < 64; e++) raw += u[s * 64 + e] * g_WvT[e * 64 + d];
        upd[t] = (raw + EPSW * sumv[d]) * zinv;
    }
    __syncthreads();

    {
        float ir = b_ih[d], iz = b_ih[64 + d], in2 = b_ih[128 + d];
        float hr = b_hh[d], hz = b_hh[64 + d], hn = b_hh[128 + d];
#pragma unroll 4
        for (int e = 0; e < 64; e++) {
            float ue = upd[s * 64 + e], pe = prev[s * 64 + e];
            const float* wi = &g_WihT[e * 192];
            const float* wh = &g_WhhT[e * 192];
            ir  += ue * wi[d];  iz += ue * wi[64 + d];  in2 += ue * wi[128 + d];
            hr  += pe * wh[d];  hz += pe * wh[64 + d];  hn  += pe * wh[128 + d];
        }
        float r = sigmoidf_(ir + hr);
        float z = sigmoidf_(iz + hz);
        float n = tanhf(in2 + r * hn);
        float hid = (1.0f - z) * n + z * prev[t];
        __syncthreads();
        Psh[t] = hid;
    }
    __syncthreads();

    if (t < 256) {
        int s2 = t >> 5, lane = t & 31;
        int e0 = lane, e1 = lane + 32;
        float v0 = Psh[s2 * 64 + e0], v1 = Psh[s2 * 64 + e1];
        float smv = v0 + v1, sq = v0 * v0 + v1 * v1;
#pragma unroll
        for (int off = 16; off; off >>= 1) {
            smv += __shfl_xor_sync(0xffffffffu, smv, off);
            sq  += __shfl_xor_sync(0xffffffffu, sq, off);
        }
        float mean = smv * (1.0f / 64.0f);
        float var  = sq * (1.0f / 64.0f) - mean * mean;
        float rstd = rsqrtf(var + LNEPS);
        u[s2 * 64 + e0] = (v0 - mean) * rstd * g_mlp[e0] + b_mlp[e0];
        u[s2 * 64 + e1] = (v1 - mean) * rstd * g_mlp[e1] + b_mlp[e1];
    }
    __syncthreads();

    {
        float h0 = b1[d], h64 = b1[d + 64];
#pragma unroll 8
        for (int e = 0; e < 64; e++) {
            float ue = u[s * 64 + e];
            h0  += ue * g_W1T[e * 128 + d];
            h64 += ue * g_W1T[e * 128 + 64 + d];
        }
        h1[s * HH + d]      = fmaxf(h0, 0.0f);
        h1[s * HH + 64 + d] = fmaxf(h64, 0.0f);
    }
    __syncthreads();

    {
        float o = Psh[t] + b2[d];
#pragma unroll 8
        for (int j = 0; j < HH; j++) o += h1[s * HH + j] * g_W2T[j * 64 + d];
        g_slots[b * 512 + t] = o;
        if (last) out[b * 512 + t] = o;
    }
}

// ---------------- launch ----------------
extern "C" void kernel_launch(void* const* d_in, const int* in_sizes, int n_in,
                              void* d_out, int out_size) {
    const float* x        = (const float*)d_in[0];
    const float* noise    = (const float*)d_in[1];
    const float* mu       = (const float*)d_in[2];
    const float* lsig     = (const float*)d_in[3];
    const float* ln_in_g  = (const float*)d_in[4];
    const float* ln_in_b  = (const float*)d_in[5];
    const float* ln_sl_g  = (const float*)d_in[6];
    const float* ln_sl_b  = (const float*)d_in[7];
    const float* ln_ml_g  = (const float*)d_in[8];
    const float* ln_ml_b  = (const float*)d_in[9];
    const float* Wq       = (const float*)d_in[10];
    const float* Wk       = (const float*)d_in[11];
    const float* Wv       = (const float*)d_in[12];
    const float* W_ih     = (const float*)d_in[13];
    const float* W_hh     = (const float*)d_in[14];
    const float* b_ih     = (const float*)d_in[15];
    const float* b_hh     = (const float*)d_in[16];
    const float* W1       = (const float*)d_in[17];
    const float* b1       = (const float*)d_in[18];
    const float* W2       = (const float*)d_in[19];
    const float* b2       = (const float*)d_in[20];
    float* out = (float*)d_out;

    cudaFuncSetAttribute(k_main, cudaFuncAttributeMaxDynamicSharedMemorySize, SMEM_K_MAIN);

    k_init<<<BB, 256>>>(noise, mu, lsig);
    k_transpose<<<48, 256>>>(W_ih, W_hh, W1, W2, Wv, Wq);
    for (int it = 0; it < 3; ++it) {
        k_qk<<<BB, 256>>>(Wk, ln_sl_g, ln_sl_b, ln_in_g, ln_in_b);
        dim3 grid(TILES, BB);
        k_main<<<grid, 128, SMEM_K_MAIN>>>(x);
        k_finalize<<<BB, 512>>>(b_ih, b_hh, b1, b2,
                                ln_in_g, ln_in_b, ln_ml_g, ln_ml_b, out, it == 2 ? 1 : 0);
    }
}

// round 12
// speedup vs baseline: 2.2516x; 1.1493x over previous
#include <cuda_runtime.h>
#include <math.h>

#define BB 32
#define NN 16384
#define SS 8
#define DD 64
#define HH 128
#define TILES 32
#define ROWS_PB 512    // rows per block = 2 chunks of 256
#define CHUNK 256
#define LNEPS 1e-5f
#define EPSW  1e-8f

typedef unsigned long long u64;

// dynamic smem carve (bytes)
#define XS_OFF   0
#define XS_BYTES (CHUNK * 16 * 16)          // 65536: float4 Xs[256][16]
#define WS_OFF   (XS_OFF + XS_BYTES)        // 65536
#define WS_BYTES (CHUNK * 32)               // 8192: ulonglong2 Ws2[256][2]
#define QP_OFF   (WS_OFF + WS_BYTES)        // 73728
#define QP_BYTES (DD * SS * 4)              // 2048: u64 qkgP[64][4] = native slot pairs
#define MS_OFF   (QP_OFF + QP_BYTES)        // 75776
#define MS_BYTES 1024
#define SMEM_K_MAIN (MS_OFF + MS_BYTES)     // 76800

// ---------------- device scratch ----------------
__device__ float  g_slots[BB * SS * DD];
__device__ float4 g_qkgT4[BB * DD * SS / 4];       // [b][e][s], s contiguous
__device__ float  g_c1[BB * SS];
__device__ float  g_c2[BB * SS];
__device__ float4 g_Pp4[BB * TILES * SS * DD / 4];
__device__ float  g_Ap[BB * TILES * SS];
__device__ float  g_Qp[BB * TILES * SS];

// transposed weights (e-major so output dim is lane-contiguous)
__device__ float  g_WihT[DD * 3 * DD];
__device__ float  g_WhhT[DD * 3 * DD];
__device__ float  g_W1T[DD * HH];
__device__ float  g_W2T[HH * DD];
__device__ float  g_WvT[DD * DD];
__device__ float  g_WqT[DD * DD];

__device__ __forceinline__ float sigmoidf_(float x) { return 1.0f / (1.0f + expf(-x)); }

// ---- f32x2 packed helpers ----
__device__ __forceinline__ u64 pk2(float lo, float hi) {
    u64 r;
    asm("mov.b64 %0, {%1, %2};" : "=l"(r) : "r"(__float_as_uint(lo)), "r"(__float_as_uint(hi)));
    return r;
}
__device__ __forceinline__ void upk2(u64 v, float& lo, float& hi) {
    unsigned a, b;
    asm("mov.b64 {%0, %1}, %2;" : "=r"(a), "=r"(b) : "l"(v));
    lo = __uint_as_float(a); hi = __uint_as_float(b);
}
__device__ __forceinline__ u64 ffma2_(u64 a, u64 b, u64 c) {
    u64 d;
    asm("fma.rn.f32x2 %0, %1, %2, %3;" : "=l"(d) : "l"(a), "l"(b), "l"(c));
    return d;
}

// ---------------- fused setup: init slots + all weight transposes ----------------
__global__ void k_setup(const float* __restrict__ noise, const float* __restrict__ mu,
                        const float* __restrict__ lsig,
                        const float* __restrict__ W_ih, const float* __restrict__ W_hh,
                        const float* __restrict__ W1,   const float* __restrict__ W2,
                        const float* __restrict__ Wv,   const float* __restrict__ Wq) {
    int i = blockIdx.x * blockDim.x + threadIdx.x;
    if (i < 12288) {
        int e = i / 192, row = i % 192;
        g_WihT[i] = W_ih[row * 64 + e];
        g_WhhT[i] = W_hh[row * 64 + e];
    }
    if (i < 8192) {
        int e = i / 128, j = i % 128;
        g_W1T[i] = W1[j * 64 + e];
        int j2 = i / 64, d = i % 64;
        g_W2T[i] = W2[d * 128 + j2];
    }
    if (i < 4096) {
        int e = i / 64, d = i % 64;
        g_WvT[i] = Wv[d * 64 + e];
        g_WqT[i] = Wq[d * 64 + e];
    }
    if (blockIdx.x < BB) {
        int b = blockIdx.x;
        for (int idx = threadIdx.x; idx < SS * DD; idx += blockDim.x)
            g_slots[b * 512 + idx] = mu[idx] + expf(lsig[idx]) * noise[b * 512 + idx];
    }
}

// ---------------- standalone qk (iteration 0 only) ----------------
__global__ void k_qk(const float* __restrict__ Wk,
                     const float* __restrict__ g_slot, const float* __restrict__ b_slot,
                     const float* __restrict__ g_in, const float* __restrict__ b_in) {
    int b = blockIdx.x, t = threadIdx.x;
    int s = t >> 5, lane = t & 31;
    __shared__ float lns[SS][DD];
    __shared__ float qm[SS][DD];

    int e0 = lane, e1 = lane + 32;
    float v0 = g_slots[b * 512 + s * 64 + e0];
    float v1 = g_slots[b * 512 + s * 64 + e1];
    float sm = v0 + v1, sq = v0 * v0 + v1 * v1;
#pragma unroll
    for (int off = 16; off; off >>= 1) {
        sm += __shfl_xor_sync(0xffffffffu, sm, off);
        sq += __shfl_xor_sync(0xffffffffu, sq, off);
    }
    float mean = sm * (1.0f / 64.0f);
    float var  = sq * (1.0f / 64.0f) - mean * mean;
    float rstd = rsqrtf(var + LNEPS);
    lns[s][e0] = (v0 - mean) * rstd * g_slot[e0] + b_slot[e0];
    lns[s][e1] = (v1 - mean) * rstd * g_slot[e1] + b_slot[e1];
    __syncthreads();

    float q0 = 0.f, q1 = 0.f;
#pragma unroll 8
    for (int e = 0; e < 64; e++) {
        float l = lns[s][e];
        q0 += l * g_WqT[e * 64 + e0];
        q1 += l * g_WqT[e * 64 + e1];
    }
    qm[s][e0] = q0 * 0.125f;
    qm[s][e1] = q1 * 0.125f;
    __syncthreads();

    float k0 = 0.f, k1 = 0.f;
#pragma unroll 8
    for (int d = 0; d < 64; d++) {
        float qv = qm[s][d];
        k0 += qv * Wk[d * 64 + e0];
        k1 += qv * Wk[d * 64 + e1];
    }
    float qkg0 = k0 * g_in[e0], qkg1 = k1 * g_in[e1];
    float* qkgT = (float*)g_qkgT4;
    qkgT[(b * 64 + e0) * 8 + s] = qkg0;
    qkgT[(b * 64 + e1) * 8 + s] = qkg1;

    float c1 = qkg0 + qkg1;
    float c2 = k0 * b_in[e0] + k1 * b_in[e1];
#pragma unroll
    for (int off = 16; off; off >>= 1) {
        c1 += __shfl_xor_sync(0xffffffffu, c1, off);
        c2 += __shfl_xor_sync(0xffffffffu, c2, off);
    }
    if (lane == 0) { g_c1[b * 8 + s] = c1; g_c2[b * 8 + s] = c2; }
}

// ---------------- main streaming pass (256 threads, 2 blocks/SM) ----------------
__global__ __launch_bounds__(256, 2) void k_main(const float* __restrict__ x) {
    extern __shared__ char smem[];
    float4*     Xs4  = (float4*)(smem + XS_OFF);      // [256][16] swizzled
    ulonglong2* Ws2  = (ulonglong2*)(smem + WS_OFF);  // [256][2]: packed slot-pair weights
    u64*        qkgP = (u64*)(smem + QP_OFF);         // [64][4]: native (s,s+1) pairs
    float*      c1s  = (float*)(smem + MS_OFF);       // 8
    float*      c2s  = c1s + 8;                       // 8
    float*      red  = c2s + 8;                       // [8][16]

    int t = threadIdx.x;
    int tile = blockIdx.x, b = blockIdx.y;

    // load qkg pairs (memory layout [e][s] already pairs slots) + consts
    if (t < 128) ((float4*)qkgP)[t] = g_qkgT4[b * 128 + t];
    if (t >= 128 && t < 136)        c1s[t - 128] = g_c1[b * 8 + t - 128];
    else if (t >= 136 && t < 144)   c2s[t - 136] = g_c2[b * 8 + t - 136];

    float Aacc[8], Qacc[8];
#pragma unroll
    for (int s = 0; s < 8; s++) { Aacc[s] = 0.f; Qacc[s] = 0.f; }
    u64 acc[16];   // [sp][j]: packed (P[2sp][4q+j], P[2sp+1][4q+j])
#pragma unroll
    for (int i = 0; i < 16; i++) acc[i] = 0ull;

    const float4* gx = (const float4*)(x + ((size_t)b * NN + (size_t)tile * ROWS_PB) * DD);
    int sub = t >> 4, q = t & 15;
    int sw = t & 15;

    __syncthreads();

    for (int chunk = 0; chunk < ROWS_PB / CHUNK; ++chunk) {
        if (chunk) __syncthreads();
        // ---- load 256 rows x 64 floats, swizzled ----
#pragma unroll
        for (int i = 0; i < 16; i++) {
            int f4 = i * 256 + t;
            int r = f4 >> 4, qq = f4 & 15;
            Xs4[r * 16 + (qq ^ (r & 15))] = gx[chunk * 4096 + f4];
        }
        __syncthreads();

        // ---- phase 1: one row per thread, slot-pair f32x2 ----
        {
            u64 lg2[4];
#pragma unroll
            for (int j = 0; j < 4; j++) lg2[j] = 0ull;
            float smv = 0.f, sqv = 0.f;
#pragma unroll
            for (int qq = 0; qq < 16; qq++) {
                float4 xv = Xs4[t * 16 + (qq ^ sw)];
#pragma unroll
                for (int k = 0; k < 4; k++) {
                    float xe = (k == 0) ? xv.x : (k == 1) ? xv.y : (k == 2) ? xv.z : xv.w;
                    u64 xx = pk2(xe, xe);
                    const ulonglong2* qp = (const ulonglong2*)(qkgP + (qq * 4 + k) * 4);
                    ulonglong2 qa = qp[0], qb = qp[1];
                    lg2[0] = ffma2_(xx, qa.x, lg2[0]);
                    lg2[1] = ffma2_(xx, qa.y, lg2[1]);
                    lg2[2] = ffma2_(xx, qb.x, lg2[2]);
                    lg2[3] = ffma2_(xx, qb.y, lg2[3]);
                    smv += xe; sqv += xe * xe;
                }
            }
            float lg[8];
#pragma unroll
            for (int j = 0; j < 4; j++) upk2(lg2[j], lg[2 * j], lg[2 * j + 1]);

            float mean = smv * (1.0f / 64.0f);
            float var  = sqv * (1.0f / 64.0f) - mean * mean;
            float rstd = rsqrtf(var + LNEPS);
            float mx = -1e30f;
#pragma unroll
            for (int s = 0; s < 8; s++) {
                lg[s] = rstd * (lg[s] - mean * c1s[s]) + c2s[s];
                mx = fmaxf(mx, lg[s]);
            }
            float es[8], ssum = 0.f;
#pragma unroll
            for (int s = 0; s < 8; s++) { es[s] = __expf(lg[s] - mx); ssum += es[s]; }
            float inv = 1.0f / ssum;
            float w[8];
#pragma unroll
            for (int s = 0; s < 8; s++) {
                float p = es[s] * inv;
                Aacc[s] += p;
                w[s] = p * rstd;
                Qacc[s] += w[s] * mean;
            }
            ulonglong2 v0, v1;
            v0.x = pk2(w[0], w[1]); v0.y = pk2(w[2], w[3]);
            v1.x = pk2(w[4], w[5]); v1.y = pk2(w[6], w[7]);
            Ws2[t * 2 + 0] = v0;
            Ws2[t * 2 + 1] = v1;
        }
        __syncthreads();

        // ---- phase 2: thread (sub, q) accumulates all 8 slots over 16 rows ----
        {
            int rbase = sub * 16;
#pragma unroll 4
            for (int i = 0; i < 16; i++) {
                int r = rbase + i;
                ulonglong2 wA = Ws2[r * 2 + 0];
                ulonglong2 wB = Ws2[r * 2 + 1];
                float4 xv = Xs4[r * 16 + (q ^ (r & 15))];
                u64 x0 = pk2(xv.x, xv.x), x1 = pk2(xv.y, xv.y);
                u64 x2 = pk2(xv.z, xv.z), x3 = pk2(xv.w, xv.w);
                acc[0]  = ffma2_(wA.x, x0, acc[0]);
                acc[1]  = ffma2_(wA.x, x1, acc[1]);
                acc[2]  = ffma2_(wA.x, x2, acc[2]);
                acc[3]  = ffma2_(wA.x, x3, acc[3]);
                acc[4]  = ffma2_(wA.y, x0, acc[4]);
                acc[5]  = ffma2_(wA.y, x1, acc[5]);
                acc[6]  = ffma2_(wA.y, x2, acc[6]);
                acc[7]  = ffma2_(wA.y, x3, acc[7]);
                acc[8]  = ffma2_(wB.x, x0, acc[8]);
                acc[9]  = ffma2_(wB.x, x1, acc[9]);
                acc[10] = ffma2_(wB.x, x2, acc[10]);
                acc[11] = ffma2_(wB.x, x3, acc[11]);
                acc[12] = ffma2_(wB.y, x0, acc[12]);
                acc[13] = ffma2_(wB.y, x1, acc[13]);
                acc[14] = ffma2_(wB.y, x2, acc[14]);
                acc[15] = ffma2_(wB.y, x3, acc[15]);
            }
        }
    }

    // ---- reduce sub-partials for P (alias Xs region) ----
    __syncthreads();
    float* Pred = (float*)(smem + XS_OFF);   // [16 sub][8 s][64 d] = 32KB
#pragma unroll
    for (int sp = 0; sp < 4; sp++) {
#pragma unroll
        for (int j = 0; j < 4; j++) {
            float lo, hi;
            upk2(acc[sp * 4 + j], lo, hi);
            Pred[(sub * 8 + 2 * sp) * 64 + 4 * q + j]     = lo;
            Pred[(sub * 8 + 2 * sp + 1) * 64 + 4 * q + j] = hi;
        }
    }
    __syncthreads();
    if (t < 128) {
        int s = t >> 4, qq = t & 15;
        float4 r4 = make_float4(0.f, 0.f, 0.f, 0.f);
#pragma unroll
        for (int sb = 0; sb < 16; sb++) {
            float4 v = ((float4*)Pred)[(sb * 8 + s) * 16 + qq];
            r4.x += v.x; r4.y += v.y; r4.z += v.z; r4.w += v.w;
        }
        g_Pp4[((b * TILES + tile) * 8 + s) * 16 + qq] = r4;
    }

    // ---- A/Q reduction (8 warps) ----
#pragma unroll
    for (int s2 = 0; s2 < 8; s2++) {
        float a = Aacc[s2], qv = Qacc[s2];
#pragma unroll
        for (int off = 16; off; off >>= 1) {
            a  += __shfl_down_sync(0xffffffffu, a, off);
            qv += __shfl_down_sync(0xffffffffu, qv, off);
        }
        Aacc[s2] = a; Qacc[s2] = qv;
    }
    int w = t >> 5, lane = t & 31;
    if (lane == 0) {
#pragma unroll
        for (int s2 = 0; s2 < 8; s2++) { red[w * 16 + s2] = Aacc[s2]; red[w * 16 + 8 + s2] = Qacc[s2]; }
    }
    __syncthreads();
    if (t < 16) {
        float v = 0.f;
#pragma unroll
        for (int ww = 0; ww < 8; ww++) v += red[ww * 16 + t];
        int base = (b * TILES + tile) * 8;
        if (t < 8) g_Ap[base + t] = v;
        else       g_Qp[base + t - 8] = v;
    }
}

// ---------------- finalize + next-iteration qk (fused) ----------------
__global__ __launch_bounds__(512) void k_finalize(
    const float* __restrict__ b_ih, const float* __restrict__ b_hh,
    const float* __restrict__ b1,   const float* __restrict__ b2,
    const float* __restrict__ g_in, const float* __restrict__ b_in,
    const float* __restrict__ g_mlp, const float* __restrict__ b_mlp,
    const float* __restrict__ Wk,
    const float* __restrict__ g_slot, const float* __restrict__ b_slot,
    float* __restrict__ out, int last) {
    int b = blockIdx.x, t = threadIdx.x;
    int s = t >> 6, d = t & 63;

    __shared__ float Psh[512];
    __shared__ float Avec[8], Qvec[8];
    __shared__ float prev[512];
    __shared__ float u[512];
    __shared__ float upd[512];
    __shared__ float sl[64], sumv[64];
    __shared__ float h1[SS * HH];

    {
        const float* Pp = (const float*)g_Pp4;
        float acc = 0.f;
#pragma unroll 8
        for (int tl = 0; tl < TILES; tl++) acc += Pp[((size_t)(b * TILES + tl)) * 512 + t];
        Psh[t] = acc;
    }
    if (t < 8) {
        float a = 0.f;
#pragma unroll 8
        for (int tl = 0; tl < TILES; tl++) a += g_Ap[(b * TILES + tl) * 8 + t];
        Avec[t] = a;
    } else if (t < 16) {
        float qv = 0.f;
#pragma unroll 8
        for (int tl = 0; tl < TILES; tl++) qv += g_Qp[(b * TILES + tl) * 8 + (t - 8)];
        Qvec[t - 8] = qv;
    }
    prev[t] = g_slots[b * 512 + t];
    __syncthreads();

    if (t < 64) {
        float pr = 0.f, qr = 0.f;
#pragma unroll
        for (int s2 = 0; s2 < 8; s2++) { pr += Psh[s2 * 64 + t]; qr += Qvec[s2]; }
        sl[t] = g_in[t] * (pr - qr) + b_in[t] * (float)NN;
    }
    u[t] = g_in[d] * (Psh[t] - Qvec[s]) + b_in[d] * Avec[s];
    __syncthreads();

    if (t < 64) {
        float sv = 0.f;
#pragma unroll 8
        for (int e = 0; e < 64; e++) sv += sl[e] * g_WvT[e * 64 + t];
        sumv[t] = sv;
    }
    __syncthreads();

    {
        float zinv = 1.0f / (Avec[s] + (float)NN * EPSW);
        float raw = 0.f;
#pragma unroll 8
        for (int e = 0; e < 64; e++) raw += u[s * 64 + e] * g_WvT[e * 64 + d];
        upd[t] = (raw + EPSW * sumv[d]) * zinv;
    }
    __syncthreads();

    {
        float ir = b_ih[d], iz = b_ih[64 + d], in2 = b_ih[128 + d];
        float hr = b_hh[d], hz = b_hh[64 + d], hn = b_hh[128 + d];
#pragma unroll 4
        for (int e = 0; e < 64; e++) {
            float ue = upd[s * 64 + e], pe = prev[s * 64 + e];
            const float* wi = &g_WihT[e * 192];
            const float* wh = &g_WhhT[e * 192];
            ir  += ue * wi[d];  iz += ue * wi[64 + d];  in2 += ue * wi[128 + d];
            hr  += pe * wh[d];  hz += pe * wh[64 + d];  hn  += pe * wh[128 + d];
        }
        float r = sigmoidf_(ir + hr);
        float z = sigmoidf_(iz + hz);
        float n = tanhf(in2 + r * hn);
        float hid = (1.0f - z) * n + z * prev[t];
        __syncthreads();
        Psh[t] = hid;
    }
    __syncthreads();

    if (t < 256) {
        int s2 = t >> 5, lane = t & 31;
        int e0 = lane, e1 = lane + 32;
        float v0 = Psh[s2 * 64 + e0], v1 = Psh[s2 * 64 + e1];
        float smv = v0 + v1, sq = v0 * v0 + v1 * v1;
#pragma unroll
        for (int off = 16; off; off >>= 1) {
            smv += __shfl_xor_sync(0xffffffffu, smv, off);
            sq  += __shfl_xor_sync(0xffffffffu, sq, off);
        }
        float mean = smv * (1.0f / 64.0f);
        float var  = sq * (1.0f / 64.0f) - mean * mean;
        float rstd = rsqrtf(var + LNEPS);
        u[s2 * 64 + e0] = (v0 - mean) * rstd * g_mlp[e0] + b_mlp[e0];
        u[s2 * 64 + e1] = (v1 - mean) * rstd * g_mlp[e1] + b_mlp[e1];
    }
    __syncthreads();

    {
        float h0 = b1[d], h64 = b1[d + 64];
#pragma unroll 8
        for (int e = 0; e < 64; e++) {
            float ue = u[s * 64 + e];
            h0  += ue * g_W1T[e * 128 + d];
            h64 += ue * g_W1T[e * 128 + 64 + d];
        }
        h1[s * HH + d]      = fmaxf(h0, 0.0f);
        h1[s * HH + 64 + d] = fmaxf(h64, 0.0f);
    }
    __syncthreads();

    {
        float o = Psh[t] + b2[d];
#pragma unroll 8
        for (int j = 0; j < HH; j++) o += h1[s * HH + j] * g_W2T[j * 64 + d];
        g_slots[b * 512 + t] = o;
        if (last) out[b * 512 + t] = o;
        upd[t] = o;                      // new slots for fused qk stage
    }
    if (last) return;
    __syncthreads();

    // ---- fused qk for NEXT iteration (first 256 threads active per stage) ----
    float* lns = h1;            // [8][64]
    float* qm  = h1 + 512;      // [8][64]
    int active = (t < 256);
    int s3 = t >> 5, lane = t & 31;
    int e0 = lane, e1 = lane + 32;
    float k0 = 0.f, k1 = 0.f;

    if (active) {
        float v0 = upd[s3 * 64 + e0];
        float v1 = upd[s3 * 64 + e1];
        float smv = v0 + v1, sq = v0 * v0 + v1 * v1;
#pragma unroll
        for (int off = 16; off; off >>= 1) {
            smv += __shfl_xor_sync(0xffffffffu, smv, off);
            sq  += __shfl_xor_sync(0xffffffffu, sq, off);
        }
        float mean = smv * (1.0f / 64.0f);
        float var  = sq * (1.0f / 64.0f) - mean * mean;
        float rstd = rsqrtf(var + LNEPS);
        lns[s3 * 64 + e0] = (v0 - mean) * rstd * g_slot[e0] + b_slot[e0];
        lns[s3 * 64 + e1] = (v1 - mean) * rstd * g_slot[e1] + b_slot[e1];
    }
    __syncthreads();
    if (active) {
        float q0 = 0.f, q1 = 0.f;
#pragma unroll 8
        for (int e = 0; e < 64; e++) {
            float l = lns[s3 * 64 + e];
            q0 += l * g_WqT[e * 64 + e0];
            q1 += l * g_WqT[e * 64 + e1];
        }
        qm[s3 * 64 + e0] = q0 * 0.125f;
        qm[s3 * 64 + e1] = q1 * 0.125f;
    }
    __syncthreads();
    if (active) {
#pragma unroll 8
        for (int dd2 = 0; dd2 < 64; dd2++) {
            float qv = qm[s3 * 64 + dd2];
            k0 += qv * Wk[dd2 * 64 + e0];
            k1 += qv * Wk[dd2 * 64 + e1];
        }
        float qkg0 = k0 * g_in[e0], qkg1 = k1 * g_in[e1];
        float* qkgT = (float*)g_qkgT4;
        qkgT[(b * 64 + e0) * 8 + s3] = qkg0;
        qkgT[(b * 64 + e1) * 8 + s3] = qkg1;

        float c1 = qkg0 + qkg1;
        float c2 = k0 * b_in[e0] + k1 * b_in[e1];
#pragma unroll
        for (int off = 16; off; off >>= 1) {
            c1 += __shfl_xor_sync(0xffffffffu, c1, off);
            c2 += __shfl_xor_sync(0xffffffffu, c2, off);
        }
        if (lane == 0) { g_c1[b * 8 + s3] = c1; g_c2[b * 8 + s3] = c2; }
    }
}

// ---------------- launch ----------------
extern "C" void kernel_launch(void* const* d_in, const int* in_sizes, int n_in,
                              void* d_out, int out_size) {
    const float* x        = (const float*)d_in[0];
    const float* noise    = (const float*)d_in[1];
    const float* mu       = (const float*)d_in[2];
    const float* lsig     = (const float*)d_in[3];
    const float* ln_in_g  = (const float*)d_in[4];
    const float* ln_in_b  = (const float*)d_in[5];
    const float* ln_sl_g  = (const float*)d_in[6];
    const float* ln_sl_b  = (const float*)d_in[7];
    const float* ln_ml_g  = (const float*)d_in[8];
    const float* ln_ml_b  = (const float*)d_in[9];
    const float* Wq       = (const float*)d_in[10];
    const float* Wk       = (const float*)d_in[11];
    const float* Wv       = (const float*)d_in[12];
    const float* W_ih     = (const float*)d_in[13];
    const float* W_hh     = (const float*)d_in[14];
    const float* b_ih     = (const float*)d_in[15];
    const float* b_hh     = (const float*)d_in[16];
    const float* W1       = (const float*)d_in[17];
    const float* b1       = (const float*)d_in[18];
    const float* W2       = (const float*)d_in[19];
    const float* b2       = (const float*)d_in[20];
    float* out = (float*)d_out;

    cudaFuncSetAttribute(k_main, cudaFuncAttributeMaxDynamicSharedMemorySize, SMEM_K_MAIN);

    k_setup<<<48, 256>>>(noise, mu, lsig, W_ih, W_hh, W1, W2, Wv, Wq);
    k_qk<<<BB, 256>>>(Wk, ln_sl_g, ln_sl_b, ln_in_g, ln_in_b);
    for (int it = 0; it < 3; ++it) {
        dim3 grid(TILES, BB);
        k_main<<<grid, 256, SMEM_K_MAIN>>>(x);
        k_finalize<<<BB, 512>>>(b_ih, b_hh, b1, b2,
                                ln_in_g, ln_in_b, ln_ml_g, ln_ml_b,
                                Wk, ln_sl_g, ln_sl_b, out, it == 2 ? 1 : 0);
    }
}

// round 13
// speedup vs baseline: 3.4774x; 1.5444x over previous
#include <cuda_runtime.h>
#include <math.h>

#define BB 32
#define NN 16384
#define SS 8
#define DD 64
#define HH 128
#define TILES 32
#define ROWS_PB 512    // rows per block = 2 chunks of 256
#define CHUNK 256
#define LNEPS 1e-5f
#define EPSW  1e-8f

typedef unsigned long long u64;

// dynamic smem carve for k_main (bytes)
#define XS_OFF   0
#define XS_BYTES (CHUNK * 16 * 16)          // 65536: float4 Xs[256][16]
#define WS_OFF   (XS_OFF + XS_BYTES)        // 65536
#define WS_BYTES (CHUNK * 32)               // 8192: ulonglong2 Ws2[256][2]
#define QP_OFF   (WS_OFF + WS_BYTES)        // 73728
#define QP_BYTES (DD * SS * 4)              // 2048: u64 qkgP[64][4] = native slot pairs
#define MS_OFF   (QP_OFF + QP_BYTES)        // 75776
#define MS_BYTES 1024
#define SMEM_K_MAIN (MS_OFF + MS_BYTES)     // 76800

// k_finalize smem layout (float offsets)
#define F_WIH   0
#define F_WHH   12288
#define F_W1    24576
#define F_W2    32768
#define F_WV    40960
#define F_WK    45056
#define F_PSH   49152
#define F_PREV  (F_PSH + 512)
#define F_U     (F_PREV + 512)
#define F_UPD   (F_U + 512)
#define F_SL    (F_UPD + 512)
#define F_SUMV  (F_SL + 64)
#define F_H1    (F_SUMV + 64)
#define F_AV    (F_H1 + 1024)
#define F_QV    (F_AV + 8)
#define F_TOTAL (F_QV + 8)                  // 52368 floats
#define SMEM_K_FIN (F_TOTAL * 4)            // 209472 bytes

// ---------------- device scratch ----------------
__device__ float  g_slots[BB * SS * DD];
__device__ float4 g_qkgT4[BB * DD * SS / 4];       // [b][e][s], s contiguous
__device__ float  g_c1[BB * SS];
__device__ float  g_c2[BB * SS];
__device__ float4 g_Pp4[BB * TILES * SS * DD / 4];
__device__ float  g_Ap[BB * TILES * SS];
__device__ float  g_Qp[BB * TILES * SS];

// transposed weights (e-major so output dim is lane-contiguous)
__device__ float  g_WihT[DD * 3 * DD];
__device__ float  g_WhhT[DD * 3 * DD];
__device__ float  g_W1T[DD * HH];
__device__ float  g_W2T[HH * DD];
__device__ float  g_WvT[DD * DD];
__device__ float  g_WqT[DD * DD];

__device__ __forceinline__ float sigmoidf_(float x) { return 1.0f / (1.0f + expf(-x)); }

// ---- f32x2 packed helpers ----
__device__ __forceinline__ u64 pk2(float lo, float hi) {
    u64 r;
    asm("mov.b64 %0, {%1, %2};" : "=l"(r) : "r"(__float_as_uint(lo)), "r"(__float_as_uint(hi)));
    return r;
}
__device__ __forceinline__ void upk2(u64 v, float& lo, float& hi) {
    unsigned a, b;
    asm("mov.b64 {%0, %1}, %2;" : "=r"(a), "=r"(b) : "l"(v));
    lo = __uint_as_float(a); hi = __uint_as_float(b);
}
__device__ __forceinline__ u64 ffma2_(u64 a, u64 b, u64 c) {
    u64 d;
    asm("fma.rn.f32x2 %0, %1, %2, %3;" : "=l"(d) : "l"(a), "l"(b), "l"(c));
    return d;
}

// ---------------- fused setup: init slots + all weight transposes ----------------
__global__ void k_setup(const float* __restrict__ noise, const float* __restrict__ mu,
                        const float* __restrict__ lsig,
                        const float* __restrict__ W_ih, const float* __restrict__ W_hh,
                        const float* __restrict__ W1,   const float* __restrict__ W2,
                        const float* __restrict__ Wv,   const float* __restrict__ Wq) {
    int i = blockIdx.x * blockDim.x + threadIdx.x;
    if (i < 12288) {
        int e = i / 192, row = i % 192;
        g_WihT[i] = W_ih[row * 64 + e];
        g_WhhT[i] = W_hh[row * 64 + e];
    }
    if (i < 8192) {
        int e = i / 128, j = i % 128;
        g_W1T[i] = W1[j * 64 + e];
        int j2 = i / 64, d = i % 64;
        g_W2T[i] = W2[d * 128 + j2];
    }
    if (i < 4096) {
        int e = i / 64, d = i % 64;
        g_WvT[i] = Wv[d * 64 + e];
        g_WqT[i] = Wq[d * 64 + e];
    }
    if (blockIdx.x < BB) {
        int b = blockIdx.x;
        for (int idx = threadIdx.x; idx < SS * DD; idx += blockDim.x)
            g_slots[b * 512 + idx] = mu[idx] + expf(lsig[idx]) * noise[b * 512 + idx];
    }
}

// ---------------- standalone qk (iteration 0 only) ----------------
__global__ void k_qk(const float* __restrict__ Wk,
                     const float* __restrict__ g_slot, const float* __restrict__ b_slot,
                     const float* __restrict__ g_in, const float* __restrict__ b_in) {
    int b = blockIdx.x, t = threadIdx.x;
    int s = t >> 5, lane = t & 31;
    __shared__ float lns[SS][DD];
    __shared__ float qm[SS][DD];

    int e0 = lane, e1 = lane + 32;
    float v0 = g_slots[b * 512 + s * 64 + e0];
    float v1 = g_slots[b * 512 + s * 64 + e1];
    float sm = v0 + v1, sq = v0 * v0 + v1 * v1;
#pragma unroll
    for (int off = 16; off; off >>= 1) {
        sm += __shfl_xor_sync(0xffffffffu, sm, off);
        sq += __shfl_xor_sync(0xffffffffu, sq, off);
    }
    float mean = sm * (1.0f / 64.0f);
    float var  = sq * (1.0f / 64.0f) - mean * mean;
    float rstd = rsqrtf(var + LNEPS);
    lns[s][e0] = (v0 - mean) * rstd * g_slot[e0] + b_slot[e0];
    lns[s][e1] = (v1 - mean) * rstd * g_slot[e1] + b_slot[e1];
    __syncthreads();

    float q0 = 0.f, q1 = 0.f;
#pragma unroll 8
    for (int e = 0; e < 64; e++) {
        float l = lns[s][e];
        q0 += l * g_WqT[e * 64 + e0];
        q1 += l * g_WqT[e * 64 + e1];
    }
    qm[s][e0] = q0 * 0.125f;
    qm[s][e1] = q1 * 0.125f;
    __syncthreads();

    float k0 = 0.f, k1 = 0.f;
#pragma unroll 8
    for (int d = 0; d < 64; d++) {
        float qv = qm[s][d];
        k0 += qv * Wk[d * 64 + e0];
        k1 += qv * Wk[d * 64 + e1];
    }
    float qkg0 = k0 * g_in[e0], qkg1 = k1 * g_in[e1];
    float* qkgT = (float*)g_qkgT4;
    qkgT[(b * 64 + e0) * 8 + s] = qkg0;
    qkgT[(b * 64 + e1) * 8 + s] = qkg1;

    float c1 = qkg0 + qkg1;
    float c2 = k0 * b_in[e0] + k1 * b_in[e1];
#pragma unroll
    for (int off = 16; off; off >>= 1) {
        c1 += __shfl_xor_sync(0xffffffffu, c1, off);
        c2 += __shfl_xor_sync(0xffffffffu, c2, off);
    }
    if (lane == 0) { g_c1[b * 8 + s] = c1; g_c2[b * 8 + s] = c2; }
}

// ---------------- main streaming pass (256 threads, 2 blocks/SM) ----------------
__global__ __launch_bounds__(256, 2) void k_main(const float* __restrict__ x) {
    extern __shared__ char smem[];
    float4*     Xs4  = (float4*)(smem + XS_OFF);      // [256][16] swizzled
    ulonglong2* Ws2  = (ulonglong2*)(smem + WS_OFF);  // [256][2]: packed slot-pair weights
    u64*        qkgP = (u64*)(smem + QP_OFF);         // [64][4]: native (s,s+1) pairs
    float*      c1s  = (float*)(smem + MS_OFF);       // 8
    float*      c2s  = c1s + 8;                       // 8
    float*      red  = c2s + 8;                       // [8][16]

    int t = threadIdx.x;
    int tile = blockIdx.x, b = blockIdx.y;

    // load qkg pairs (memory layout [e][s] already pairs slots) + consts
    if (t < 128) ((float4*)qkgP)[t] = g_qkgT4[b * 128 + t];
    if (t >= 128 && t < 136)        c1s[t - 128] = g_c1[b * 8 + t - 128];
    else if (t >= 136 && t < 144)   c2s[t - 136] = g_c2[b * 8 + t - 136];

    float Aacc[8], Qacc[8];
#pragma unroll
    for (int s = 0; s < 8; s++) { Aacc[s] = 0.f; Qacc[s] = 0.f; }
    u64 acc[16];   // [sp][j]: packed (P[2sp][4q+j], P[2sp+1][4q+j])
#pragma unroll
    for (int i = 0; i < 16; i++) acc[i] = 0ull;

    const float4* gx = (const float4*)(x + ((size_t)b * NN + (size_t)tile * ROWS_PB) * DD);
    int sub = t >> 4, q = t & 15;
    int sw = t & 15;

    __syncthreads();

    for (int chunk = 0; chunk < ROWS_PB / CHUNK; ++chunk) {
        if (chunk) __syncthreads();
        // ---- load 256 rows x 64 floats, swizzled ----
#pragma unroll
        for (int i = 0; i < 16; i++) {
            int f4 = i * 256 + t;
            int r = f4 >> 4, qq = f4 & 15;
            Xs4[r * 16 + (qq ^ (r & 15))] = gx[chunk * 4096 + f4];
        }
        __syncthreads();

        // ---- phase 1: one row per thread, slot-pair f32x2 ----
        {
            u64 lg2[4];
#pragma unroll
            for (int j = 0; j < 4; j++) lg2[j] = 0ull;
            float smv = 0.f, sqv = 0.f;
#pragma unroll
            for (int qq = 0; qq < 16; qq++) {
                float4 xv = Xs4[t * 16 + (qq ^ sw)];
#pragma unroll
                for (int k = 0; k < 4; k++) {
                    float xe = (k == 0) ? xv.x : (k == 1) ? xv.y : (k == 2) ? xv.z : xv.w;
                    u64 xx = pk2(xe, xe);
                    const ulonglong2* qp = (const ulonglong2*)(qkgP + (qq * 4 + k) * 4);
                    ulonglong2 qa = qp[0], qb = qp[1];
                    lg2[0] = ffma2_(xx, qa.x, lg2[0]);
                    lg2[1] = ffma2_(xx, qa.y, lg2[1]);
                    lg2[2] = ffma2_(xx, qb.x, lg2[2]);
                    lg2[3] = ffma2_(xx, qb.y, lg2[3]);
                    smv += xe; sqv += xe * xe;
                }
            }
            float lg[8];
#pragma unroll
            for (int j = 0; j < 4; j++) upk2(lg2[j], lg[2 * j], lg[2 * j + 1]);

            float mean = smv * (1.0f / 64.0f);
            float var  = sqv * (1.0f / 64.0f) - mean * mean;
            float rstd = rsqrtf(var + LNEPS);
            float mx = -1e30f;
#pragma unroll
            for (int s = 0; s < 8; s++) {
                lg[s] = rstd * (lg[s] - mean * c1s[s]) + c2s[s];
                mx = fmaxf(mx, lg[s]);
            }
            float es[8], ssum = 0.f;
#pragma unroll
            for (int s = 0; s < 8; s++) { es[s] = __expf(lg[s] - mx); ssum += es[s]; }
            float inv = 1.0f / ssum;
            float w[8];
#pragma unroll
            for (int s = 0; s < 8; s++) {
                float p = es[s] * inv;
                Aacc[s] += p;
                w[s] = p * rstd;
                Qacc[s] += w[s] * mean;
            }
            ulonglong2 v0, v1;
            v0.x = pk2(w[0], w[1]); v0.y = pk2(w[2], w[3]);
            v1.x = pk2(w[4], w[5]); v1.y = pk2(w[6], w[7]);
            Ws2[t * 2 + 0] = v0;
            Ws2[t * 2 + 1] = v1;
        }
        __syncthreads();

        // ---- phase 2: thread (sub, q) accumulates all 8 slots over 16 rows ----
        {
            int rbase = sub * 16;
#pragma unroll 4
            for (int i = 0; i < 16; i++) {
                int r = rbase + i;
                ulonglong2 wA = Ws2[r * 2 + 0];
                ulonglong2 wB = Ws2[r * 2 + 1];
                float4 xv = Xs4[r * 16 + (q ^ (r & 15))];
                u64 x0 = pk2(xv.x, xv.x), x1 = pk2(xv.y, xv.y);
                u64 x2 = pk2(xv.z, xv.z), x3 = pk2(xv.w, xv.w);
                acc[0]  = ffma2_(wA.x, x0, acc[0]);
                acc[1]  = ffma2_(wA.x, x1, acc[1]);
                acc[2]  = ffma2_(wA.x, x2, acc[2]);
                acc[3]  = ffma2_(wA.x, x3, acc[3]);
                acc[4]  = ffma2_(wA.y, x0, acc[4]);
                acc[5]  = ffma2_(wA.y, x1, acc[5]);
                acc[6]  = ffma2_(wA.y, x2, acc[6]);
                acc[7]  = ffma2_(wA.y, x3, acc[7]);
                acc[8]  = ffma2_(wB.x, x0, acc[8]);
                acc[9]  = ffma2_(wB.x, x1, acc[9]);
                acc[10] = ffma2_(wB.x, x2, acc[10]);
                acc[11] = ffma2_(wB.x, x3, acc[11]);
                acc[12] = ffma2_(wB.y, x0, acc[12]);
                acc[13] = ffma2_(wB.y, x1, acc[13]);
                acc[14] = ffma2_(wB.y, x2, acc[14]);
                acc[15] = ffma2_(wB.y, x3, acc[15]);
            }
        }
    }

    // ---- reduce sub-partials for P (alias Xs region) ----
    __syncthreads();
    float* Pred = (float*)(smem + XS_OFF);   // [16 sub][8 s][64 d] = 32KB
#pragma unroll
    for (int sp = 0; sp < 4; sp++) {
#pragma unroll
        for (int j = 0; j < 4; j++) {
            float lo, hi;
            upk2(acc[sp * 4 + j], lo, hi);
            Pred[(sub * 8 + 2 * sp) * 64 + 4 * q + j]     = lo;
            Pred[(sub * 8 + 2 * sp + 1) * 64 + 4 * q + j] = hi;
        }
    }
    __syncthreads();
    if (t < 128) {
        int s = t >> 4, qq = t & 15;
        float4 r4 = make_float4(0.f, 0.f, 0.f, 0.f);
#pragma unroll
        for (int sb = 0; sb < 16; sb++) {
            float4 v = ((float4*)Pred)[(sb * 8 + s) * 16 + qq];
            r4.x += v.x; r4.y += v.y; r4.z += v.z; r4.w += v.w;
        }
        g_Pp4[((b * TILES + tile) * 8 + s) * 16 + qq] = r4;
    }

    // ---- A/Q reduction (8 warps) ----
#pragma unroll
    for (int s2 = 0; s2 < 8; s2++) {
        float a = Aacc[s2], qv = Qacc[s2];
#pragma unroll
        for (int off = 16; off; off >>= 1) {
            a  += __shfl_down_sync(0xffffffffu, a, off);
            qv += __shfl_down_sync(0xffffffffu, qv, off);
        }
        Aacc[s2] = a; Qacc[s2] = qv;
    }
    int w = t >> 5, lane = t & 31;
    if (lane == 0) {
#pragma unroll
        for (int s2 = 0; s2 < 8; s2++) { red[w * 16 + s2] = Aacc[s2]; red[w * 16 + 8 + s2] = Qacc[s2]; }
    }
    __syncthreads();
    if (t < 16) {
        float v = 0.f;
#pragma unroll
        for (int ww = 0; ww < 8; ww++) v += red[ww * 16 + t];
        int base = (b * TILES + tile) * 8;
        if (t < 8) g_Ap[base + t] = v;
        else       g_Qp[base + t - 8] = v;
    }
}

// ---------------- finalize + next-iteration qk (fused, weights staged to smem) ----------------
__global__ __launch_bounds__(512) void k_finalize(
    const float* __restrict__ b_ih, const float* __restrict__ b_hh,
    const float* __restrict__ b1,   const float* __restrict__ b2,
    const float* __restrict__ g_in, const float* __restrict__ b_in,
    const float* __restrict__ g_mlp, const float* __restrict__ b_mlp,
    const float* __restrict__ Wk,
    const float* __restrict__ g_slot, const float* __restrict__ b_slot,
    float* __restrict__ out, int last) {
    extern __shared__ float fsm[];
    int b = blockIdx.x, t = threadIdx.x;
    int s = t >> 6, d = t & 63;

    float* sWih = fsm + F_WIH;
    float* sWhh = fsm + F_WHH;
    float* sW1  = fsm + F_W1;
    float* sW2  = fsm + F_W2;
    float* sWv  = fsm + F_WV;
    float* sWk  = fsm + F_WK;
    float* Psh  = fsm + F_PSH;
    float* prev = fsm + F_PREV;
    float* u    = fsm + F_U;
    float* upd  = fsm + F_UPD;
    float* sl   = fsm + F_SL;
    float* sumv = fsm + F_SUMV;
    float* h1   = fsm + F_H1;
    float* Avec = fsm + F_AV;
    float* Qvec = fsm + F_QV;

    // ---- cooperative weight staging (coalesced, high MLP) ----
#pragma unroll
    for (int i = 0; i < 6; i++) ((float4*)sWih)[i * 512 + t] = ((const float4*)g_WihT)[i * 512 + t];
#pragma unroll
    for (int i = 0; i < 6; i++) ((float4*)sWhh)[i * 512 + t] = ((const float4*)g_WhhT)[i * 512 + t];
#pragma unroll
    for (int i = 0; i < 4; i++) ((float4*)sW1)[i * 512 + t]  = ((const float4*)g_W1T)[i * 512 + t];
#pragma unroll
    for (int i = 0; i < 4; i++) ((float4*)sW2)[i * 512 + t]  = ((const float4*)g_W2T)[i * 512 + t];
#pragma unroll
    for (int i = 0; i < 2; i++) ((float4*)sWv)[i * 512 + t]  = ((const float4*)g_WvT)[i * 512 + t];
#pragma unroll
    for (int i = 0; i < 2; i++) ((float4*)sWk)[i * 512 + t]  = ((const float4*)Wk)[i * 512 + t];

    // ---- reduce per-tile partials (overlaps with staging loads) ----
    {
        const float* Pp = (const float*)g_Pp4;
        float acc = 0.f;
#pragma unroll 8
        for (int tl = 0; tl < TILES; tl++) acc += Pp[((size_t)(b * TILES + tl)) * 512 + t];
        Psh[t] = acc;
    }
    if (t < 8) {
        float a = 0.f;
#pragma unroll 8
        for (int tl = 0; tl < TILES; tl++) a += g_Ap[(b * TILES + tl) * 8 + t];
        Avec[t] = a;
    } else if (t < 16) {
        float qv = 0.f;
#pragma unroll 8
        for (int tl = 0; tl < TILES; tl++) qv += g_Qp[(b * TILES + tl) * 8 + (t - 8)];
        Qvec[t - 8] = qv;
    }
    prev[t] = g_slots[b * 512 + t];
    __syncthreads();

    if (t < 64) {
        float pr = 0.f, qr = 0.f;
#pragma unroll
        for (int s2 = 0; s2 < 8; s2++) { pr += Psh[s2 * 64 + t]; qr += Qvec[s2]; }
        sl[t] = g_in[t] * (pr - qr) + b_in[t] * (float)NN;
    }
    u[t] = g_in[d] * (Psh[t] - Qvec[s]) + b_in[d] * Avec[s];
    __syncthreads();

    if (t < 64) {
        float sv = 0.f;
#pragma unroll 8
        for (int e = 0; e < 64; e++) sv += sl[e] * sWv[e * 64 + t];
        sumv[t] = sv;
    }
    __syncthreads();

    {
        float zinv = 1.0f / (Avec[s] + (float)NN * EPSW);
        float raw = 0.f;
#pragma unroll 8
        for (int e = 0; e < 64; e++) raw += u[s * 64 + e] * sWv[e * 64 + d];
        upd[t] = (raw + EPSW * sumv[d]) * zinv;
    }
    __syncthreads();

    {
        float ir = b_ih[d], iz = b_ih[64 + d], in2 = b_ih[128 + d];
        float hr = b_hh[d], hz = b_hh[64 + d], hn = b_hh[128 + d];
#pragma unroll 8
        for (int e = 0; e < 64; e++) {
            float ue = upd[s * 64 + e], pe = prev[s * 64 + e];
            const float* wi = &sWih[e * 192];
            const float* wh = &sWhh[e * 192];
            ir  += ue * wi[d];  iz += ue * wi[64 + d];  in2 += ue * wi[128 + d];
            hr  += pe * wh[d];  hz += pe * wh[64 + d];  hn  += pe * wh[128 + d];
        }
        float r = sigmoidf_(ir + hr);
        float z = sigmoidf_(iz + hz);
        float n = tanhf(in2 + r * hn);
        float hid = (1.0f - z) * n + z * prev[t];
        __syncthreads();
        Psh[t] = hid;
    }
    __syncthreads();

    if (t < 256) {
        int s2 = t >> 5, lane = t & 31;
        int e0 = lane, e1 = lane + 32;
        float v0 = Psh[s2 * 64 + e0], v1 = Psh[s2 * 64 + e1];
        float smv = v0 + v1, sq = v0 * v0 + v1 * v1;
#pragma unroll
        for (int off = 16; off; off >>= 1) {
            smv += __shfl_xor_sync(0xffffffffu, smv, off);
            sq  += __shfl_xor_sync(0xffffffffu, sq, off);
        }
        float mean = smv * (1.0f / 64.0f);
        float var  = sq * (1.0f / 64.0f) - mean * mean;
        float rstd = rsqrtf(var + LNEPS);
        u[s2 * 64 + e0] = (v0 - mean) * rstd * g_mlp[e0] + b_mlp[e0];
        u[s2 * 64 + e1] = (v1 - mean) * rstd * g_mlp[e1] + b_mlp[e1];
    }
    __syncthreads();

    {
        float h0 = b1[d], h64 = b1[d + 64];
#pragma unroll 8
        for (int e = 0; e < 64; e++) {
            float ue = u[s * 64 + e];
            h0  += ue * sW1[e * 128 + d];
            h64 += ue * sW1[e * 128 + 64 + d];
        }
        h1[s * HH + d]      = fmaxf(h0, 0.0f);
        h1[s * HH + 64 + d] = fmaxf(h64, 0.0f);
    }
    __syncthreads();

    {
        float o = Psh[t] + b2[d];
#pragma unroll 8
        for (int j = 0; j < HH; j++) o += h1[s * HH + j] * sW2[j * 64 + d];
        g_slots[b * 512 + t] = o;
        if (last) out[b * 512 + t] = o;
        upd[t] = o;                      // new slots for fused qk stage
    }
    if (last) return;
    __syncthreads();

    // ---- fused qk for NEXT iteration (first 256 threads active per stage) ----
    float* lns = h1;            // [8][64]
    float* qm  = h1 + 512;      // [8][64]
    int active = (t < 256);
    int s3 = t >> 5, lane = t & 31;
    int e0 = lane, e1 = lane + 32;
    float k0 = 0.f, k1 = 0.f;

    if (active) {
        float v0 = upd[s3 * 64 + e0];
        float v1 = upd[s3 * 64 + e1];
        float smv = v0 + v1, sq = v0 * v0 + v1 * v1;
#pragma unroll
        for (int off = 16; off; off >>= 1) {
            smv += __shfl_xor_sync(0xffffffffu, smv, off);
            sq  += __shfl_xor_sync(0xffffffffu, sq, off);
        }
        float mean = smv * (1.0f / 64.0f);
        float var  = sq * (1.0f / 64.0f) - mean * mean;
        float rstd = rsqrtf(var + LNEPS);
        lns[s3 * 64 + e0] = (v0 - mean) * rstd * g_slot[e0] + b_slot[e0];
        lns[s3 * 64 + e1] = (v1 - mean) * rstd * g_slot[e1] + b_slot[e1];
    }
    __syncthreads();
    if (active) {
        float q0 = 0.f, q1 = 0.f;
#pragma unroll 8
        for (int e = 0; e < 64; e++) {
            float l = lns[s3 * 64 + e];
            q0 += l * g_WqT[e * 64 + e0];
            q1 += l * g_WqT[e * 64 + e1];
        }
        qm[s3 * 64 + e0] = q0 * 0.125f;
        qm[s3 * 64 + e1] = q1 * 0.125f;
    }
    __syncthreads();
    if (active) {
#pragma unroll 8
        for (int dd2 = 0; dd2 < 64; dd2++) {
            float qv = qm[s3 * 64 + dd2];
            k0 += qv * sWk[dd2 * 64 + e0];
            k1 += qv * sWk[dd2 * 64 + e1];
        }
        float qkg0 = k0 * g_in[e0], qkg1 = k1 * g_in[e1];
        float* qkgT = (float*)g_qkgT4;
        qkgT[(b * 64 + e0) * 8 + s3] = qkg0;
        qkgT[(b * 64 + e1) * 8 + s3] = qkg1;

        float c1 = qkg0 + qkg1;
        float c2 = k0 * b_in[e0] + k1 * b_in[e1];
#pragma unroll
        for (int off = 16; off; off >>= 1) {
            c1 += __shfl_xor_sync(0xffffffffu, c1, off);
            c2 += __shfl_xor_sync(0xffffffffu, c2, off);
        }
        if (lane == 0) { g_c1[b * 8 + s3] = c1; g_c2[b * 8 + s3] = c2; }
    }
}

// ---------------- launch ----------------
extern "C" void kernel_launch(void* const* d_in, const int* in_sizes, int n_in,
                              void* d_out, int out_size) {
    const float* x        = (const float*)d_in[0];
    const float* noise    = (const float*)d_in[1];
    const float* mu       = (const float*)d_in[2];
    const float* lsig     = (const float*)d_in[3];
    const float* ln_in_g  = (const float*)d_in[4];
    const float* ln_in_b  = (const float*)d_in[5];
    const float* ln_sl_g  = (const float*)d_in[6];
    const float* ln_sl_b  = (const float*)d_in[7];
    const float* ln_ml_g  = (const float*)d_in[8];
    const float* ln_ml_b  = (const float*)d_in[9];
    const float* Wq       = (const float*)d_in[10];
    const float* Wk       = (const float*)d_in[11];
    const float* Wv       = (const float*)d_in[12];
    const float* W_ih     = (const float*)d_in[13];
    const float* W_hh     = (const float*)d_in[14];
    const float* b_ih     = (const float*)d_in[15];
    const float* b_hh     = (const float*)d_in[16];
    const float* W1       = (const float*)d_in[17];
    const float* b1       = (const float*)d_in[18];
    const float* W2       = (const float*)d_in[19];
    const float* b2       = (const float*)d_in[20];
    float* out = (float*)d_out;

    cudaFuncSetAttribute(k_main, cudaFuncAttributeMaxDynamicSharedMemorySize, SMEM_K_MAIN);
    cudaFuncSetAttribute(k_finalize, cudaFuncAttributeMaxDynamicSharedMemorySize, SMEM_K_FIN);

    k_setup<<<48, 256>>>(noise, mu, lsig, W_ih, W_hh, W1, W2, Wv, Wq);
    k_qk<<<BB, 256>>>(Wk, ln_sl_g, ln_sl_b, ln_in_g, ln_in_b);
    for (int it = 0; it < 3; ++it) {
        dim3 grid(TILES, BB);
        k_main<<<grid, 256, SMEM_K_MAIN>>>(x);
        k_finalize<<<BB, 512, SMEM_K_FIN>>>(b_ih, b_hh, b1, b2,
                                ln_in_g, ln_in_b, ln_ml_g, ln_ml_b,
                                Wk, ln_sl_g, ln_sl_b, out, it == 2 ? 1 : 0);
    }
}